// round 1
// baseline (speedup 1.0000x reference)
#include <cuda_runtime.h>
#include <math.h>

#define NHEAD 12
#define HD    128
#define DMODEL 1536
#define SCTX  256
#define SINP  2048
#define NTOK  2304
#define NB    2

// ------------------------- scratch (device globals; no allocs allowed) ----
__device__ float g_qkv[(size_t)NB * NTOK * 3 * DMODEL];   // [b][tok][4608], ctx tokens first
__device__ float g_q[(size_t)NB * NHEAD * NTOK * HD];     // [b*h][tok][128]
__device__ float g_k[(size_t)NB * NHEAD * NTOK * HD];
__device__ float g_v[(size_t)NB * NHEAD * NTOK * HD];
__device__ float g_o[(size_t)NB * NTOK * DMODEL];         // [b][tok][1536]

// ------------------------- generic fp32 SGEMM with affine row remap -------
// C[crow(m)][bn+*] = A[arow(m)][:] @ B[:, bn+*] + bias
// row map: r(m) = (m/S)*Stride + Off + m%S   (S=1<<30 -> identity)
__device__ __forceinline__ int maprow(int m, int S, int off, int st) {
    return (m / S) * st + off + (m % S);
}

__global__ __launch_bounds__(256, 2) void sgemm_k(
    const float* __restrict__ A, const float* __restrict__ Bm,
    const float* __restrict__ bias, float* __restrict__ C,
    int M, int N, int K,
    int aS, int aOff, int aStride,
    int cS, int cOff, int cStride, int ldc)
{
    __shared__ float As[16][128];
    __shared__ float Bs[16][128];
    int tid = threadIdx.x;
    int bm = blockIdx.y * 128, bn = blockIdx.x * 128;

    int lr = tid >> 2;             // A load row within tile (0..63, +64 for 2nd)
    int k4 = (tid & 3) * 4;        // k-subcolumn
    const float* a0 = A + (size_t)maprow(bm + lr,      aS, aOff, aStride) * K + k4;
    const float* a1 = A + (size_t)maprow(bm + lr + 64, aS, aOff, aStride) * K + k4;

    int brow = tid >> 5;           // B load row (0..7, +8 for 2nd)
    int bcol = (tid & 31) * 4;
    const float* bp = Bm + (size_t)brow * N + bn + bcol;

    int tyc = tid >> 4, txc = tid & 15;
    float acc[8][8] = {};

    for (int k0 = 0; k0 < K; k0 += 16) {
        float4 av0 = *(const float4*)(a0 + k0);
        float4 av1 = *(const float4*)(a1 + k0);
        float4 bv0 = *(const float4*)(bp + (size_t)k0 * N);
        float4 bv1 = *(const float4*)(bp + (size_t)(k0 + 8) * N);
        As[k4 + 0][lr] = av0.x; As[k4 + 1][lr] = av0.y;
        As[k4 + 2][lr] = av0.z; As[k4 + 3][lr] = av0.w;
        As[k4 + 0][lr + 64] = av1.x; As[k4 + 1][lr + 64] = av1.y;
        As[k4 + 2][lr + 64] = av1.z; As[k4 + 3][lr + 64] = av1.w;
        *(float4*)&Bs[brow][bcol]     = bv0;
        *(float4*)&Bs[brow + 8][bcol] = bv1;
        __syncthreads();
#pragma unroll
        for (int kk = 0; kk < 16; kk++) {
            float4 x0 = *(const float4*)&As[kk][tyc * 8];
            float4 x1 = *(const float4*)&As[kk][tyc * 8 + 4];
            float4 y0 = *(const float4*)&Bs[kk][txc * 8];
            float4 y1 = *(const float4*)&Bs[kk][txc * 8 + 4];
            float ar[8] = {x0.x, x0.y, x0.z, x0.w, x1.x, x1.y, x1.z, x1.w};
            float br[8] = {y0.x, y0.y, y0.z, y0.w, y1.x, y1.y, y1.z, y1.w};
#pragma unroll
            for (int i = 0; i < 8; i++)
#pragma unroll
                for (int j = 0; j < 8; j++)
                    acc[i][j] += ar[i] * br[j];
        }
        __syncthreads();
    }
#pragma unroll
    for (int i = 0; i < 8; i++) {
        int crow = maprow(bm + tyc * 8 + i, cS, cOff, cStride);
        float* cp = C + (size_t)crow * ldc + bn + txc * 8;
#pragma unroll
        for (int j = 0; j < 8; j++)
            cp[j] = acc[i][j] + bias[bn + txc * 8 + j];
    }
}

// ------------------------- fused RMSNorm + RoPE + head transpose ----------
// one block per (batch, token); 512 threads; norm over full DMODEL=1536
__global__ __launch_bounds__(512) void norm_rope_k(
    const float* __restrict__ qkv,
    const float* __restrict__ qs_in, const float* __restrict__ ks_in,
    const float* __restrict__ qs_ctx, const float* __restrict__ ks_ctx,
    float* __restrict__ Q, float* __restrict__ K, float* __restrict__ V)
{
    __shared__ float sq[DMODEL], sk[DMODEL];
    __shared__ float cs_tab[64], sn_tab[64];
    __shared__ float wq[16], wk[16], ssum[2];

    int bt = blockIdx.x;
    int b = bt / NTOK, t = bt - b * NTOK;
    const float* row = qkv + (size_t)bt * (3 * DMODEL);
    bool is_ctx = (t < SCTX);
    const float* qs = is_ctx ? qs_ctx : qs_in;
    const float* ks = is_ctx ? ks_ctx : ks_in;
    int tid = threadIdx.x;

    // accurate RoPE table: inv_freq rounded to f32 (matches fp32 reference),
    // angle = f32(t * inv_freq) like the reference, then fp64 sincos of it.
    if (tid < 64) {
        float invf = (float)pow(10000.0, -(double)tid / 64.0);
        float ang = (float)t * invf;
        cs_tab[tid] = (float)cos((double)ang);
        sn_tab[tid] = (float)sin((double)ang);
    }

    float aq = 0.f, ak = 0.f;
    float qv[3], kv[3], vv[3];
#pragma unroll
    for (int j = 0; j < 3; j++) {
        int i = tid + j * 512;
        qv[j] = row[i];
        kv[j] = row[DMODEL + i];
        vv[j] = row[2 * DMODEL + i];
        aq += qv[j] * qv[j];
        ak += kv[j] * kv[j];
    }
#pragma unroll
    for (int off = 16; off; off >>= 1) {
        aq += __shfl_xor_sync(0xffffffffu, aq, off);
        ak += __shfl_xor_sync(0xffffffffu, ak, off);
    }
    int wid = tid >> 5, lane = tid & 31;
    if (!lane) { wq[wid] = aq; wk[wid] = ak; }
    __syncthreads();
    if (tid == 0) {
        float s1 = 0.f, s2 = 0.f;
#pragma unroll
        for (int w = 0; w < 16; w++) { s1 += wq[w]; s2 += wk[w]; }
        ssum[0] = s1; ssum[1] = s2;
    }
    __syncthreads();
    float rq = rsqrtf(ssum[0] * (1.0f / DMODEL) + 1e-6f);
    float rk = rsqrtf(ssum[1] * (1.0f / DMODEL) + 1e-6f);
#pragma unroll
    for (int j = 0; j < 3; j++) {
        int i = tid + j * 512;
        sq[i] = qv[j] * rq * qs[i];
        sk[i] = kv[j] * rk * ks[i];
    }
    __syncthreads();
#pragma unroll
    for (int j = 0; j < 3; j++) {
        int i = tid + j * 512;
        int h = i >> 7, d = i & 127;
        int jj = d & 63;
        float cv = cs_tab[jj], sv = sn_tab[jj];
        int base = h * HD;
        float qo, ko;
        if (d < 64) {
            qo = sq[base + d] * cv - sq[base + d + 64] * sv;
            ko = sk[base + d] * cv - sk[base + d + 64] * sv;
        } else {
            qo = sq[base + d] * cv + sq[base + d - 64] * sv;
            ko = sk[base + d] * cv + sk[base + d - 64] * sv;
        }
        size_t o = ((size_t)(b * NHEAD + h) * NTOK + t) * HD + d;
        Q[o] = qo; K[o] = ko; V[o] = vv[j];
    }
}

// ------------------------- flash attention fp32, BQ=BK=64 ----------------
__global__ __launch_bounds__(256, 2) void attn_k(
    const float* __restrict__ Q, const float* __restrict__ K,
    const float* __restrict__ V, float* __restrict__ O)
{
    extern __shared__ float sm[];
    float* Qt = sm;                 // [128][68]  (transposed: [kk][row])
    float* Kt = sm + 128 * 68;      // [128][68]; P tile aliases this after use
    float* Vs = Kt + 128 * 68;      // [64][128]
    float* Ps = Kt;                 // [64][64]

    int tid = threadIdx.x;
    int qt = blockIdx.x, bh = blockIdx.y;
    int b = bh / NHEAD, h = bh - b * NHEAD;
    const float* Qb = Q + ((size_t)bh * NTOK + qt * 64) * HD;
    const float* Kb = K + (size_t)bh * NTOK * HD;
    const float* Vb = V + (size_t)bh * NTOK * HD;

#pragma unroll
    for (int i = 0; i < 8; i++) {            // load+transpose Q (64x128)
        int f = tid + i * 256;
        int r = f >> 5, c4 = (f & 31) * 4;
        float4 qv = *(const float4*)&Qb[r * HD + c4];
        Qt[(c4 + 0) * 68 + r] = qv.x;
        Qt[(c4 + 1) * 68 + r] = qv.y;
        Qt[(c4 + 2) * 68 + r] = qv.z;
        Qt[(c4 + 3) * 68 + r] = qv.w;
    }

    int ty = tid >> 4, tx = tid & 15;        // 16x16 thread grid
    float o[4][8];
    float m[4], l[4];
#pragma unroll
    for (int i = 0; i < 4; i++) {
        m[i] = -INFINITY; l[i] = 0.f;
#pragma unroll
        for (int j = 0; j < 8; j++) o[i][j] = 0.f;
    }

    for (int kt = 0; kt < 36; kt++) {
        __syncthreads();                     // prev tile fully consumed (+Q visible on iter 0)
#pragma unroll
        for (int i = 0; i < 8; i++) {        // load K (transposed) and V
            int f = tid + i * 256;
            int r = f >> 5, c4 = (f & 31) * 4;
            float4 kv = *(const float4*)&Kb[(kt * 64 + r) * HD + c4];
            Kt[(c4 + 0) * 68 + r] = kv.x;
            Kt[(c4 + 1) * 68 + r] = kv.y;
            Kt[(c4 + 2) * 68 + r] = kv.z;
            Kt[(c4 + 3) * 68 + r] = kv.w;
            *(float4*)&Vs[r * HD + c4] = *(const float4*)&Vb[(kt * 64 + r) * HD + c4];
        }
        __syncthreads();

        float s[4][4] = {};
#pragma unroll 8
        for (int kk = 0; kk < 128; kk++) {   // S = Q K^T  (outer-product form)
            float4 qv = *(const float4*)&Qt[kk * 68 + ty * 4];
            float4 kv = *(const float4*)&Kt[kk * 68 + tx * 4];
            float qa[4] = {qv.x, qv.y, qv.z, qv.w};
            float ka[4] = {kv.x, kv.y, kv.z, kv.w};
#pragma unroll
            for (int i = 0; i < 4; i++)
#pragma unroll
                for (int j = 0; j < 4; j++)
                    s[i][j] += qa[i] * ka[j];
        }
        __syncthreads();                     // Kt reads done -> safe to alias Ps

        const float sc = 0.08838834764831845f;  // 1/sqrt(128)
        float al[4];
#pragma unroll
        for (int i = 0; i < 4; i++) {
#pragma unroll
            for (int j = 0; j < 4; j++) s[i][j] *= sc;
            float mx = fmaxf(fmaxf(s[i][0], s[i][1]), fmaxf(s[i][2], s[i][3]));
#pragma unroll
            for (int msk = 8; msk; msk >>= 1)
                mx = fmaxf(mx, __shfl_xor_sync(0xffffffffu, mx, msk));
            float mn = fmaxf(m[i], mx);
            al[i] = expf(m[i] - mn);
            m[i] = mn;
            float rs = 0.f;
#pragma unroll
            for (int j = 0; j < 4; j++) {
                s[i][j] = expf(s[i][j] - mn);
                rs += s[i][j];
            }
#pragma unroll
            for (int msk = 8; msk; msk >>= 1)
                rs += __shfl_xor_sync(0xffffffffu, rs, msk);
            l[i] = l[i] * al[i] + rs;
        }
#pragma unroll
        for (int i = 0; i < 4; i++) {
#pragma unroll
            for (int j = 0; j < 4; j++)
                Ps[(ty * 4 + i) * 64 + tx * 4 + j] = s[i][j];
#pragma unroll
            for (int j = 0; j < 8; j++) o[i][j] *= al[i];
        }
        __syncthreads();

#pragma unroll 4
        for (int k = 0; k < 64; k++) {       // O += P V
            float p0 = Ps[(ty * 4 + 0) * 64 + k];
            float p1 = Ps[(ty * 4 + 1) * 64 + k];
            float p2 = Ps[(ty * 4 + 2) * 64 + k];
            float p3 = Ps[(ty * 4 + 3) * 64 + k];
            float4 v0 = *(const float4*)&Vs[k * HD + tx * 8];
            float4 v1 = *(const float4*)&Vs[k * HD + tx * 8 + 4];
            float va[8] = {v0.x, v0.y, v0.z, v0.w, v1.x, v1.y, v1.z, v1.w};
#pragma unroll
            for (int j = 0; j < 8; j++) {
                o[0][j] += p0 * va[j];
                o[1][j] += p1 * va[j];
                o[2][j] += p2 * va[j];
                o[3][j] += p3 * va[j];
            }
        }
    }

#pragma unroll
    for (int i = 0; i < 4; i++) {
        float inv = 1.0f / l[i];
        int row = qt * 64 + ty * 4 + i;
        float* op = O + ((size_t)(b * NTOK + row)) * DMODEL + h * HD + tx * 8;
#pragma unroll
        for (int j = 0; j < 8; j++) op[j] = o[i][j] * inv;
    }
}

// ------------------------- launch -----------------------------------------
extern "C" void kernel_launch(void* const* d_in, const int* in_sizes, int n_in,
                              void* d_out, int out_size)
{
    const float* input   = (const float*)d_in[0];
    const float* context = (const float*)d_in[1];
    const float* Wqi = (const float*)d_in[2];
    const float* bqi = (const float*)d_in[3];
    const float* Wqc = (const float*)d_in[4];
    const float* bqc = (const float*)d_in[5];
    const float* qsi = (const float*)d_in[6];
    const float* ksi = (const float*)d_in[7];
    const float* qsc = (const float*)d_in[8];
    const float* ksc = (const float*)d_in[9];
    const float* Woi = (const float*)d_in[10];
    const float* boi = (const float*)d_in[11];
    const float* Woc = (const float*)d_in[12];
    const float* boc = (const float*)d_in[13];
    float* out = (float*)d_out;

    float *qkv, *q, *k, *v, *o;
    cudaGetSymbolAddress((void**)&qkv, g_qkv);
    cudaGetSymbolAddress((void**)&q,   g_q);
    cudaGetSymbolAddress((void**)&k,   g_k);
    cudaGetSymbolAddress((void**)&v,   g_v);
    cudaGetSymbolAddress((void**)&o,   g_o);

    const int BIG = 1 << 30;

    // QKV projections (write into concatenated [b][tok][4608] buffer)
    sgemm_k<<<dim3(36, 32), 256>>>(input, Wqi, bqi, qkv,
                                   4096, 4608, 1536,
                                   BIG, 0, 0,
                                   SINP, SCTX, NTOK, 4608);
    sgemm_k<<<dim3(36, 4), 256>>>(context, Wqc, bqc, qkv,
                                  512, 4608, 1536,
                                  BIG, 0, 0,
                                  SCTX, 0, NTOK, 4608);

    // RMSNorm + RoPE + transpose into [b*h][tok][128]
    norm_rope_k<<<NB * NTOK, 512>>>(qkv, qsi, ksi, qsc, ksc, q, k, v);

    // attention
    cudaFuncSetAttribute(attn_k, cudaFuncAttributeMaxDynamicSharedMemorySize, 102400);
    attn_k<<<dim3(36, NB * NHEAD), 256, 102400>>>(q, k, v, o);

    // output projections straight into d_out (input part, then context part)
    sgemm_k<<<dim3(12, 32), 256>>>(o, Woi, boi, out,
                                   4096, 1536, 1536,
                                   SINP, SCTX, NTOK,
                                   BIG, 0, 0, 1536);
    sgemm_k<<<dim3(12, 4), 256>>>(o, Woc, boc, out + (size_t)NB * SINP * DMODEL,
                                  512, 1536, 1536,
                                  SCTX, 0, NTOK,
                                  BIG, 0, 0, 1536);
}

// round 2
// speedup vs baseline: 1.3271x; 1.3271x over previous
#include <cuda_runtime.h>
#include <math.h>

#define NHEAD 12
#define HD    128
#define DMODEL 1536
#define SCTX  256
#define SINP  2048
#define NTOK  2304
#define NB    2

// ------------------------- scratch (device globals; no allocs allowed) ----
__device__ float g_qkv[(size_t)NB * NTOK * 3 * DMODEL];   // [b][tok][4608], ctx tokens first
__device__ float g_q[(size_t)NB * NHEAD * NTOK * HD];     // [b*h][tok][128]
__device__ float g_k[(size_t)NB * NHEAD * NTOK * HD];
__device__ float g_v[(size_t)NB * NHEAD * NTOK * HD];
__device__ float g_o[(size_t)NB * NTOK * DMODEL];         // [b][tok][1536]

// row map: r(m) = (m/S)*Stride + Off + m%S   (S=1<<30 -> identity)
__device__ __forceinline__ int maprow(int m, int S, int off, int st) {
    return (m / S) * st + off + (m % S);
}

__device__ __forceinline__ float tf32_rn(float x) {
    unsigned r;
    asm("cvt.rna.tf32.f32 %0, %1;" : "=r"(r) : "f"(x));
    return __uint_as_float(r);
}

__device__ __forceinline__ void mma_tf32(float* d, const unsigned* a, const unsigned* b) {
    asm volatile(
        "mma.sync.aligned.m16n8k8.row.col.f32.tf32.tf32.f32 "
        "{%0,%1,%2,%3},{%4,%5,%6,%7},{%8,%9},{%0,%1,%2,%3};"
        : "+f"(d[0]), "+f"(d[1]), "+f"(d[2]), "+f"(d[3])
        : "r"(a[0]), "r"(a[1]), "r"(a[2]), "r"(a[3]), "r"(b[0]), "r"(b[1]));
}

// ------------------------- tf32 tensor-core GEMM with affine row remap ----
// C[crow(m)][bn+*] = A[arow(m)][:] @ B[:, bn+*] + bias
// BM=BN=128, BK=16, 256 threads, warp grid 4(m)x2(n), warp tile 32x64.
__global__ __launch_bounds__(256, 2) void sgemm_tc(
    const float* __restrict__ A, const float* __restrict__ Bm,
    const float* __restrict__ bias, float* __restrict__ C,
    int M, int N, int K,
    int aS, int aOff, int aStride,
    int cS, int cOff, int cStride, int ldc)
{
    __shared__ float As[2][16][128];   // [k][m ^ ((k&3)<<3)]  (XOR swizzle, stride 128)
    __shared__ float Bs[2][16][136];   // [k][n], pad -> stride 136 (==8 mod 32)

    int tid = threadIdx.x;
    int bm = blockIdx.y * 128, bn = blockIdx.x * 128;

    // ---- gmem load mapping ----
    // A: thread owns rows (arow, arow+64), k-phase kseg; loads k = kseg + 4i (i=0..3)
    int arow = tid >> 2;          // 0..63
    int kseg = tid & 3;           // 0..3
    const float* aptr0 = A + (size_t)maprow(bm + arow,      aS, aOff, aStride) * K + kseg;
    const float* aptr1 = A + (size_t)maprow(bm + arow + 64, aS, aOff, aStride) * K + kseg;
    // B: thread owns rows (brow, brow+8), 4 consecutive cols
    int brow = tid >> 5;          // 0..7
    int bcol = (tid & 31) * 4;
    const float* bptr = Bm + (size_t)brow * N + bn + bcol;

    // ---- warp/lane decomposition ----
    int warp = tid >> 5;
    int wm = warp & 3, wn = warp >> 2;    // warp tile: rows wm*32, cols wn*64
    int lane = tid & 31;
    int lg = lane >> 2, lt = lane & 3;    // group / thread-in-group

    float acc[2][8][4];
#pragma unroll
    for (int mi = 0; mi < 2; mi++)
#pragma unroll
        for (int nf = 0; nf < 8; nf++)
#pragma unroll
            for (int r = 0; r < 4; r++) acc[mi][nf][r] = 0.f;

    int ntiles = K / 16;

    float ra0[4], ra1[4];
    float4 rb0, rb1;

    // prologue: load tile 0 and commit to buffer 0
#pragma unroll
    for (int i = 0; i < 4; i++) { ra0[i] = aptr0[4 * i]; ra1[i] = aptr1[4 * i]; }
    rb0 = *(const float4*)(bptr);
    rb1 = *(const float4*)(bptr + (size_t)8 * N);
#pragma unroll
    for (int i = 0; i < 4; i++) {
        As[0][kseg + 4 * i][arow        ^ (kseg << 3)] = tf32_rn(ra0[i]);
        As[0][kseg + 4 * i][(arow + 64) ^ (kseg << 3)] = tf32_rn(ra1[i]);
    }
    {
        float4 c0 = make_float4(tf32_rn(rb0.x), tf32_rn(rb0.y), tf32_rn(rb0.z), tf32_rn(rb0.w));
        float4 c1 = make_float4(tf32_rn(rb1.x), tf32_rn(rb1.y), tf32_rn(rb1.z), tf32_rn(rb1.w));
        *(float4*)&Bs[0][brow][bcol]     = c0;
        *(float4*)&Bs[0][brow + 8][bcol] = c1;
    }
    __syncthreads();

    for (int t = 0; t < ntiles; t++) {
        int cur = t & 1;
        // prefetch next tile into registers
        if (t + 1 < ntiles) {
            const float* a0 = aptr0 + (size_t)(t + 1) * 16;
            const float* a1 = aptr1 + (size_t)(t + 1) * 16;
#pragma unroll
            for (int i = 0; i < 4; i++) { ra0[i] = a0[4 * i]; ra1[i] = a1[4 * i]; }
            const float* bp = bptr + (size_t)(t + 1) * 16 * N;
            rb0 = *(const float4*)(bp);
            rb1 = *(const float4*)(bp + (size_t)8 * N);
        }

        // compute on current buffer
#pragma unroll
        for (int kf = 0; kf < 2; kf++) {
            int kb = kf * 8;
            unsigned af[2][4];
#pragma unroll
            for (int mi = 0; mi < 2; mi++) {
                int m0 = wm * 32 + mi * 16 + lg;
                af[mi][0] = __float_as_uint(As[cur][kb + lt]    [m0       ^ (lt << 3)]);
                af[mi][1] = __float_as_uint(As[cur][kb + lt]    [(m0 + 8) ^ (lt << 3)]);
                af[mi][2] = __float_as_uint(As[cur][kb + lt + 4][m0       ^ (lt << 3)]);
                af[mi][3] = __float_as_uint(As[cur][kb + lt + 4][(m0 + 8) ^ (lt << 3)]);
            }
            unsigned bf[8][2];
#pragma unroll
            for (int nf = 0; nf < 8; nf++) {
                int n = wn * 64 + nf * 8 + lg;
                bf[nf][0] = __float_as_uint(Bs[cur][kb + lt][n]);
                bf[nf][1] = __float_as_uint(Bs[cur][kb + lt + 4][n]);
            }
#pragma unroll
            for (int mi = 0; mi < 2; mi++)
#pragma unroll
                for (int nf = 0; nf < 8; nf++)
                    mma_tf32(acc[mi][nf], af[mi], bf[nf]);
        }

        // commit prefetched tile to the alternate buffer
        if (t + 1 < ntiles) {
            int alt = cur ^ 1;
#pragma unroll
            for (int i = 0; i < 4; i++) {
                As[alt][kseg + 4 * i][arow        ^ (kseg << 3)] = tf32_rn(ra0[i]);
                As[alt][kseg + 4 * i][(arow + 64) ^ (kseg << 3)] = tf32_rn(ra1[i]);
            }
            float4 c0 = make_float4(tf32_rn(rb0.x), tf32_rn(rb0.y), tf32_rn(rb0.z), tf32_rn(rb0.w));
            float4 c1 = make_float4(tf32_rn(rb1.x), tf32_rn(rb1.y), tf32_rn(rb1.z), tf32_rn(rb1.w));
            *(float4*)&Bs[alt][brow][bcol]     = c0;
            *(float4*)&Bs[alt][brow + 8][bcol] = c1;
        }
        __syncthreads();
    }

    // ---- epilogue: bias + remapped store ----
#pragma unroll
    for (int mi = 0; mi < 2; mi++) {
        int r0 = bm + wm * 32 + mi * 16 + lg;
        int cr0 = maprow(r0,     cS, cOff, cStride);
        int cr1 = maprow(r0 + 8, cS, cOff, cStride);
#pragma unroll
        for (int nf = 0; nf < 8; nf++) {
            int cn = bn + wn * 64 + nf * 8 + 2 * lt;
            float b0 = bias[cn], b1 = bias[cn + 1];
            float2 v0 = make_float2(acc[mi][nf][0] + b0, acc[mi][nf][1] + b1);
            float2 v1 = make_float2(acc[mi][nf][2] + b0, acc[mi][nf][3] + b1);
            *(float2*)&C[(size_t)cr0 * ldc + cn] = v0;
            *(float2*)&C[(size_t)cr1 * ldc + cn] = v1;
        }
    }
}

// ------------------------- fused RMSNorm + RoPE + head transpose ----------
// one block per (batch, token); 512 threads; norm over full DMODEL=1536
__global__ __launch_bounds__(512) void norm_rope_k(
    const float* __restrict__ qkv,
    const float* __restrict__ qs_in, const float* __restrict__ ks_in,
    const float* __restrict__ qs_ctx, const float* __restrict__ ks_ctx,
    float* __restrict__ Q, float* __restrict__ K, float* __restrict__ V)
{
    __shared__ float sq[DMODEL], sk[DMODEL];
    __shared__ float cs_tab[64], sn_tab[64];
    __shared__ float wq[16], wk[16], ssum[2];

    int bt = blockIdx.x;
    int b = bt / NTOK, t = bt - b * NTOK;
    const float* row = qkv + (size_t)bt * (3 * DMODEL);
    bool is_ctx = (t < SCTX);
    const float* qs = is_ctx ? qs_ctx : qs_in;
    const float* ks = is_ctx ? ks_ctx : ks_in;
    int tid = threadIdx.x;

    if (tid < 64) {
        float invf = (float)pow(10000.0, -(double)tid / 64.0);
        float ang = (float)t * invf;
        cs_tab[tid] = (float)cos((double)ang);
        sn_tab[tid] = (float)sin((double)ang);
    }

    float aq = 0.f, ak = 0.f;
    float qv[3], kv[3], vv[3];
#pragma unroll
    for (int j = 0; j < 3; j++) {
        int i = tid + j * 512;
        qv[j] = row[i];
        kv[j] = row[DMODEL + i];
        vv[j] = row[2 * DMODEL + i];
        aq += qv[j] * qv[j];
        ak += kv[j] * kv[j];
    }
#pragma unroll
    for (int off = 16; off; off >>= 1) {
        aq += __shfl_xor_sync(0xffffffffu, aq, off);
        ak += __shfl_xor_sync(0xffffffffu, ak, off);
    }
    int wid = tid >> 5, lane = tid & 31;
    if (!lane) { wq[wid] = aq; wk[wid] = ak; }
    __syncthreads();
    if (tid == 0) {
        float s1 = 0.f, s2 = 0.f;
#pragma unroll
        for (int w = 0; w < 16; w++) { s1 += wq[w]; s2 += wk[w]; }
        ssum[0] = s1; ssum[1] = s2;
    }
    __syncthreads();
    float rq = rsqrtf(ssum[0] * (1.0f / DMODEL) + 1e-6f);
    float rk = rsqrtf(ssum[1] * (1.0f / DMODEL) + 1e-6f);
#pragma unroll
    for (int j = 0; j < 3; j++) {
        int i = tid + j * 512;
        sq[i] = qv[j] * rq * qs[i];
        sk[i] = kv[j] * rk * ks[i];
    }
    __syncthreads();
#pragma unroll
    for (int j = 0; j < 3; j++) {
        int i = tid + j * 512;
        int h = i >> 7, d = i & 127;
        int jj = d & 63;
        float cv = cs_tab[jj], sv = sn_tab[jj];
        int base = h * HD;
        float qo, ko;
        if (d < 64) {
            qo = sq[base + d] * cv - sq[base + d + 64] * sv;
            ko = sk[base + d] * cv - sk[base + d + 64] * sv;
        } else {
            qo = sq[base + d] * cv + sq[base + d - 64] * sv;
            ko = sk[base + d] * cv + sk[base + d - 64] * sv;
        }
        size_t o = ((size_t)(b * NHEAD + h) * NTOK + t) * HD + d;
        Q[o] = qo; K[o] = ko; V[o] = vv[j];
    }
}

// ------------------------- flash attention fp32, BQ=BK=64 ----------------
__global__ __launch_bounds__(256, 2) void attn_k(
    const float* __restrict__ Q, const float* __restrict__ K,
    const float* __restrict__ V, float* __restrict__ O)
{
    extern __shared__ float sm[];
    float* Qt = sm;                 // [128][68]  (transposed: [kk][row])
    float* Kt = sm + 128 * 68;      // [128][68]; P tile aliases this after use
    float* Vs = Kt + 128 * 68;      // [64][128]
    float* Ps = Kt;                 // [64][64]

    int tid = threadIdx.x;
    int qt = blockIdx.x, bh = blockIdx.y;
    int b = bh / NHEAD, h = bh - b * NHEAD;
    const float* Qb = Q + ((size_t)bh * NTOK + qt * 64) * HD;
    const float* Kb = K + (size_t)bh * NTOK * HD;
    const float* Vb = V + (size_t)bh * NTOK * HD;

#pragma unroll
    for (int i = 0; i < 8; i++) {            // load+transpose Q (64x128)
        int f = tid + i * 256;
        int r = f >> 5, c4 = (f & 31) * 4;
        float4 qv = *(const float4*)&Qb[r * HD + c4];
        Qt[(c4 + 0) * 68 + r] = qv.x;
        Qt[(c4 + 1) * 68 + r] = qv.y;
        Qt[(c4 + 2) * 68 + r] = qv.z;
        Qt[(c4 + 3) * 68 + r] = qv.w;
    }

    int ty = tid >> 4, tx = tid & 15;        // 16x16 thread grid
    float o[4][8];
    float m[4], l[4];
#pragma unroll
    for (int i = 0; i < 4; i++) {
        m[i] = -INFINITY; l[i] = 0.f;
#pragma unroll
        for (int j = 0; j < 8; j++) o[i][j] = 0.f;
    }

    for (int kt = 0; kt < 36; kt++) {
        __syncthreads();                     // prev tile fully consumed (+Q visible on iter 0)
#pragma unroll
        for (int i = 0; i < 8; i++) {        // load K (transposed) and V
            int f = tid + i * 256;
            int r = f >> 5, c4 = (f & 31) * 4;
            float4 kv = *(const float4*)&Kb[(kt * 64 + r) * HD + c4];
            Kt[(c4 + 0) * 68 + r] = kv.x;
            Kt[(c4 + 1) * 68 + r] = kv.y;
            Kt[(c4 + 2) * 68 + r] = kv.z;
            Kt[(c4 + 3) * 68 + r] = kv.w;
            *(float4*)&Vs[r * HD + c4] = *(const float4*)&Vb[(kt * 64 + r) * HD + c4];
        }
        __syncthreads();

        float s[4][4] = {};
#pragma unroll 8
        for (int kk = 0; kk < 128; kk++) {   // S = Q K^T  (outer-product form)
            float4 qv = *(const float4*)&Qt[kk * 68 + ty * 4];
            float4 kv = *(const float4*)&Kt[kk * 68 + tx * 4];
            float qa[4] = {qv.x, qv.y, qv.z, qv.w};
            float ka[4] = {kv.x, kv.y, kv.z, kv.w};
#pragma unroll
            for (int i = 0; i < 4; i++)
#pragma unroll
                for (int j = 0; j < 4; j++)
                    s[i][j] += qa[i] * ka[j];
        }
        __syncthreads();                     // Kt reads done -> safe to alias Ps

        const float sc = 0.08838834764831845f;  // 1/sqrt(128)
        float al[4];
#pragma unroll
        for (int i = 0; i < 4; i++) {
#pragma unroll
            for (int j = 0; j < 4; j++) s[i][j] *= sc;
            float mx = fmaxf(fmaxf(s[i][0], s[i][1]), fmaxf(s[i][2], s[i][3]));
#pragma unroll
            for (int msk = 8; msk; msk >>= 1)
                mx = fmaxf(mx, __shfl_xor_sync(0xffffffffu, mx, msk));
            float mn = fmaxf(m[i], mx);
            al[i] = expf(m[i] - mn);
            m[i] = mn;
            float rs = 0.f;
#pragma unroll
            for (int j = 0; j < 4; j++) {
                s[i][j] = expf(s[i][j] - mn);
                rs += s[i][j];
            }
#pragma unroll
            for (int msk = 8; msk; msk >>= 1)
                rs += __shfl_xor_sync(0xffffffffu, rs, msk);
            l[i] = l[i] * al[i] + rs;
        }
#pragma unroll
        for (int i = 0; i < 4; i++) {
#pragma unroll
            for (int j = 0; j < 4; j++)
                Ps[(ty * 4 + i) * 64 + tx * 4 + j] = s[i][j];
#pragma unroll
            for (int j = 0; j < 8; j++) o[i][j] *= al[i];
        }
        __syncthreads();

#pragma unroll 4
        for (int k = 0; k < 64; k++) {       // O += P V
            float p0 = Ps[(ty * 4 + 0) * 64 + k];
            float p1 = Ps[(ty * 4 + 1) * 64 + k];
            float p2 = Ps[(ty * 4 + 2) * 64 + k];
            float p3 = Ps[(ty * 4 + 3) * 64 + k];
            float4 v0 = *(const float4*)&Vs[k * HD + tx * 8];
            float4 v1 = *(const float4*)&Vs[k * HD + tx * 8 + 4];
            float va[8] = {v0.x, v0.y, v0.z, v0.w, v1.x, v1.y, v1.z, v1.w};
#pragma unroll
            for (int j = 0; j < 8; j++) {
                o[0][j] += p0 * va[j];
                o[1][j] += p1 * va[j];
                o[2][j] += p2 * va[j];
                o[3][j] += p3 * va[j];
            }
        }
    }

#pragma unroll
    for (int i = 0; i < 4; i++) {
        float inv = 1.0f / l[i];
        int row = qt * 64 + ty * 4 + i;
        float* op = O + ((size_t)(b * NTOK + row)) * DMODEL + h * HD + tx * 8;
#pragma unroll
        for (int j = 0; j < 8; j++) op[j] = o[i][j] * inv;
    }
}

// ------------------------- launch -----------------------------------------
extern "C" void kernel_launch(void* const* d_in, const int* in_sizes, int n_in,
                              void* d_out, int out_size)
{
    const float* input   = (const float*)d_in[0];
    const float* context = (const float*)d_in[1];
    const float* Wqi = (const float*)d_in[2];
    const float* bqi = (const float*)d_in[3];
    const float* Wqc = (const float*)d_in[4];
    const float* bqc = (const float*)d_in[5];
    const float* qsi = (const float*)d_in[6];
    const float* ksi = (const float*)d_in[7];
    const float* qsc = (const float*)d_in[8];
    const float* ksc = (const float*)d_in[9];
    const float* Woi = (const float*)d_in[10];
    const float* boi = (const float*)d_in[11];
    const float* Woc = (const float*)d_in[12];
    const float* boc = (const float*)d_in[13];
    float* out = (float*)d_out;

    float *qkv, *q, *k, *v, *o;
    cudaGetSymbolAddress((void**)&qkv, g_qkv);
    cudaGetSymbolAddress((void**)&q,   g_q);
    cudaGetSymbolAddress((void**)&k,   g_k);
    cudaGetSymbolAddress((void**)&v,   g_v);
    cudaGetSymbolAddress((void**)&o,   g_o);

    const int BIG = 1 << 30;

    // QKV projections (write into concatenated [b][tok][4608] buffer)
    sgemm_tc<<<dim3(36, 32), 256>>>(input, Wqi, bqi, qkv,
                                    4096, 4608, 1536,
                                    BIG, 0, 0,
                                    SINP, SCTX, NTOK, 4608);
    sgemm_tc<<<dim3(36, 4), 256>>>(context, Wqc, bqc, qkv,
                                   512, 4608, 1536,
                                   BIG, 0, 0,
                                   SCTX, 0, NTOK, 4608);

    // RMSNorm + RoPE + transpose into [b*h][tok][128]
    norm_rope_k<<<NB * NTOK, 512>>>(qkv, qsi, ksi, qsc, ksc, q, k, v);

    // attention
    cudaFuncSetAttribute(attn_k, cudaFuncAttributeMaxDynamicSharedMemorySize, 102400);
    attn_k<<<dim3(36, NB * NHEAD), 256, 102400>>>(q, k, v, o);

    // output projections straight into d_out (input part, then context part)
    sgemm_tc<<<dim3(12, 32), 256>>>(o, Woi, boi, out,
                                    4096, 1536, 1536,
                                    SINP, SCTX, NTOK,
                                    BIG, 0, 0, 1536);
    sgemm_tc<<<dim3(12, 4), 256>>>(o, Woc, boc, out + (size_t)NB * SINP * DMODEL,
                                   512, 1536, 1536,
                                   SCTX, 0, NTOK,
                                   BIG, 0, 0, 1536);
}

// round 4
// speedup vs baseline: 1.7825x; 1.3431x over previous
#include <cuda_runtime.h>
#include <math.h>

#define NHEAD 12
#define HD    128
#define DMODEL 1536
#define SCTX  256
#define SINP  2048
#define NTOK  2304
#define NB    2

// ------------------------- scratch (device globals; no allocs allowed) ----
__device__ float g_qkv[(size_t)NB * NTOK * 3 * DMODEL];   // [b][tok][4608], ctx tokens first
__device__ float g_q[(size_t)NB * NHEAD * NTOK * HD];     // [b*h][tok][128]
__device__ float g_k[(size_t)NB * NHEAD * NTOK * HD];
__device__ float g_v[(size_t)NB * NHEAD * NTOK * HD];
__device__ float g_o[(size_t)NB * NTOK * DMODEL];         // [b][tok][1536]

// row map: r(m) = (m/S)*Stride + Off + m%S   (S=1<<30 -> identity)
__device__ __forceinline__ int maprow(int m, int S, int off, int st) {
    return (m / S) * st + off + (m % S);
}

__device__ __forceinline__ float tf32_rn(float x) {
    unsigned r;
    asm("cvt.rna.tf32.f32 %0, %1;" : "=r"(r) : "f"(x));
    return __uint_as_float(r);
}

__device__ __forceinline__ void mma_tf32(float* d, const unsigned* a, const unsigned* b) {
    asm volatile(
        "mma.sync.aligned.m16n8k8.row.col.f32.tf32.tf32.f32 "
        "{%0,%1,%2,%3},{%4,%5,%6,%7},{%8,%9},{%0,%1,%2,%3};"
        : "+f"(d[0]), "+f"(d[1]), "+f"(d[2]), "+f"(d[3])
        : "r"(a[0]), "r"(a[1]), "r"(a[2]), "r"(a[3]), "r"(b[0]), "r"(b[1]));
}

// packed f32x2 helpers (FFMA2 path — only reachable via PTX f32x2 ops)
__device__ __forceinline__ unsigned long long ffma2(
    unsigned long long a, unsigned long long b, unsigned long long c) {
    unsigned long long d;
    asm("fma.rn.f32x2 %0, %1, %2, %3;" : "=l"(d) : "l"(a), "l"(b), "l"(c));
    return d;
}
__device__ __forceinline__ unsigned long long fmul2(
    unsigned long long a, unsigned long long b) {
    unsigned long long d;
    asm("mul.rn.f32x2 %0, %1, %2;" : "=l"(d) : "l"(a), "l"(b));
    return d;
}
__device__ __forceinline__ unsigned long long bcast2(float x) {
    unsigned long long d;
    asm("mov.b64 %0, {%1, %1};" : "=l"(d) : "f"(x));
    return d;
}

// ------------------------- tf32 tensor-core GEMM with affine row remap ----
__global__ __launch_bounds__(256, 2) void sgemm_tc(
    const float* __restrict__ A, const float* __restrict__ Bm,
    const float* __restrict__ bias, float* __restrict__ C,
    int M, int N, int K,
    int aS, int aOff, int aStride,
    int cS, int cOff, int cStride, int ldc)
{
    __shared__ float As[2][16][128];   // [k][m ^ ((k&3)<<3)]
    __shared__ float Bs[2][16][136];   // [k][n], pad

    int tid = threadIdx.x;
    int bm = blockIdx.y * 128, bn = blockIdx.x * 128;

    int arow = tid >> 2;
    int kseg = tid & 3;
    const float* aptr0 = A + (size_t)maprow(bm + arow,      aS, aOff, aStride) * K + kseg;
    const float* aptr1 = A + (size_t)maprow(bm + arow + 64, aS, aOff, aStride) * K + kseg;
    int brow = tid >> 5;
    int bcol = (tid & 31) * 4;
    const float* bptr = Bm + (size_t)brow * N + bn + bcol;

    int warp = tid >> 5;
    int wm = warp & 3, wn = warp >> 2;
    int lane = tid & 31;
    int lg = lane >> 2, lt = lane & 3;

    float acc[2][8][4];
#pragma unroll
    for (int mi = 0; mi < 2; mi++)
#pragma unroll
        for (int nf = 0; nf < 8; nf++)
#pragma unroll
            for (int r = 0; r < 4; r++) acc[mi][nf][r] = 0.f;

    int ntiles = K / 16;

    float ra0[4], ra1[4];
    float4 rb0, rb1;

#pragma unroll
    for (int i = 0; i < 4; i++) { ra0[i] = aptr0[4 * i]; ra1[i] = aptr1[4 * i]; }
    rb0 = *(const float4*)(bptr);
    rb1 = *(const float4*)(bptr + (size_t)8 * N);
#pragma unroll
    for (int i = 0; i < 4; i++) {
        As[0][kseg + 4 * i][arow        ^ (kseg << 3)] = tf32_rn(ra0[i]);
        As[0][kseg + 4 * i][(arow + 64) ^ (kseg << 3)] = tf32_rn(ra1[i]);
    }
    {
        float4 c0 = make_float4(tf32_rn(rb0.x), tf32_rn(rb0.y), tf32_rn(rb0.z), tf32_rn(rb0.w));
        float4 c1 = make_float4(tf32_rn(rb1.x), tf32_rn(rb1.y), tf32_rn(rb1.z), tf32_rn(rb1.w));
        *(float4*)&Bs[0][brow][bcol]     = c0;
        *(float4*)&Bs[0][brow + 8][bcol] = c1;
    }
    __syncthreads();

    for (int t = 0; t < ntiles; t++) {
        int cur = t & 1;
        if (t + 1 < ntiles) {
            const float* a0 = aptr0 + (size_t)(t + 1) * 16;
            const float* a1 = aptr1 + (size_t)(t + 1) * 16;
#pragma unroll
            for (int i = 0; i < 4; i++) { ra0[i] = a0[4 * i]; ra1[i] = a1[4 * i]; }
            const float* bp = bptr + (size_t)(t + 1) * 16 * N;
            rb0 = *(const float4*)(bp);
            rb1 = *(const float4*)(bp + (size_t)8 * N);
        }

#pragma unroll
        for (int kf = 0; kf < 2; kf++) {
            int kb = kf * 8;
            unsigned af[2][4];
#pragma unroll
            for (int mi = 0; mi < 2; mi++) {
                int m0 = wm * 32 + mi * 16 + lg;
                af[mi][0] = __float_as_uint(As[cur][kb + lt]    [m0       ^ (lt << 3)]);
                af[mi][1] = __float_as_uint(As[cur][kb + lt]    [(m0 + 8) ^ (lt << 3)]);
                af[mi][2] = __float_as_uint(As[cur][kb + lt + 4][m0       ^ (lt << 3)]);
                af[mi][3] = __float_as_uint(As[cur][kb + lt + 4][(m0 + 8) ^ (lt << 3)]);
            }
            unsigned bf[8][2];
#pragma unroll
            for (int nf = 0; nf < 8; nf++) {
                int n = wn * 64 + nf * 8 + lg;
                bf[nf][0] = __float_as_uint(Bs[cur][kb + lt][n]);
                bf[nf][1] = __float_as_uint(Bs[cur][kb + lt + 4][n]);
            }
#pragma unroll
            for (int mi = 0; mi < 2; mi++)
#pragma unroll
                for (int nf = 0; nf < 8; nf++)
                    mma_tf32(acc[mi][nf], af[mi], bf[nf]);
        }

        if (t + 1 < ntiles) {
            int alt = cur ^ 1;
#pragma unroll
            for (int i = 0; i < 4; i++) {
                As[alt][kseg + 4 * i][arow        ^ (kseg << 3)] = tf32_rn(ra0[i]);
                As[alt][kseg + 4 * i][(arow + 64) ^ (kseg << 3)] = tf32_rn(ra1[i]);
            }
            float4 c0 = make_float4(tf32_rn(rb0.x), tf32_rn(rb0.y), tf32_rn(rb0.z), tf32_rn(rb0.w));
            float4 c1 = make_float4(tf32_rn(rb1.x), tf32_rn(rb1.y), tf32_rn(rb1.z), tf32_rn(rb1.w));
            *(float4*)&Bs[alt][brow][bcol]     = c0;
            *(float4*)&Bs[alt][brow + 8][bcol] = c1;
        }
        __syncthreads();
    }

#pragma unroll
    for (int mi = 0; mi < 2; mi++) {
        int r0 = bm + wm * 32 + mi * 16 + lg;
        int cr0 = maprow(r0,     cS, cOff, cStride);
        int cr1 = maprow(r0 + 8, cS, cOff, cStride);
#pragma unroll
        for (int nf = 0; nf < 8; nf++) {
            int cn = bn + wn * 64 + nf * 8 + 2 * lt;
            float b0 = bias[cn], b1 = bias[cn + 1];
            float2 v0 = make_float2(acc[mi][nf][0] + b0, acc[mi][nf][1] + b1);
            float2 v1 = make_float2(acc[mi][nf][2] + b0, acc[mi][nf][3] + b1);
            *(float2*)&C[(size_t)cr0 * ldc + cn] = v0;
            *(float2*)&C[(size_t)cr1 * ldc + cn] = v1;
        }
    }
}

// ------------------------- fused RMSNorm + RoPE + head transpose ----------
__global__ __launch_bounds__(512) void norm_rope_k(
    const float* __restrict__ qkv,
    const float* __restrict__ qs_in, const float* __restrict__ ks_in,
    const float* __restrict__ qs_ctx, const float* __restrict__ ks_ctx,
    float* __restrict__ Q, float* __restrict__ K, float* __restrict__ V)
{
    __shared__ float sq[DMODEL], sk[DMODEL];
    __shared__ float cs_tab[64], sn_tab[64];
    __shared__ float wq[16], wk[16], ssum[2];

    int bt = blockIdx.x;
    int b = bt / NTOK, t = bt - b * NTOK;
    const float* row = qkv + (size_t)bt * (3 * DMODEL);
    bool is_ctx = (t < SCTX);
    const float* qs = is_ctx ? qs_ctx : qs_in;
    const float* ks = is_ctx ? ks_ctx : ks_in;
    int tid = threadIdx.x;

    if (tid < 64) {
        float invf = (float)pow(10000.0, -(double)tid / 64.0);
        float ang = (float)t * invf;
        cs_tab[tid] = (float)cos((double)ang);
        sn_tab[tid] = (float)sin((double)ang);
    }

    float aq = 0.f, ak = 0.f;
    float qv[3], kv[3], vv[3];
#pragma unroll
    for (int j = 0; j < 3; j++) {
        int i = tid + j * 512;
        qv[j] = row[i];
        kv[j] = row[DMODEL + i];
        vv[j] = row[2 * DMODEL + i];
        aq += qv[j] * qv[j];
        ak += kv[j] * kv[j];
    }
#pragma unroll
    for (int off = 16; off; off >>= 1) {
        aq += __shfl_xor_sync(0xffffffffu, aq, off);
        ak += __shfl_xor_sync(0xffffffffu, ak, off);
    }
    int wid = tid >> 5, lane = tid & 31;
    if (!lane) { wq[wid] = aq; wk[wid] = ak; }
    __syncthreads();
    if (tid == 0) {
        float s1 = 0.f, s2 = 0.f;
#pragma unroll
        for (int w = 0; w < 16; w++) { s1 += wq[w]; s2 += wk[w]; }
        ssum[0] = s1; ssum[1] = s2;
    }
    __syncthreads();
    float rq = rsqrtf(ssum[0] * (1.0f / DMODEL) + 1e-6f);
    float rk = rsqrtf(ssum[1] * (1.0f / DMODEL) + 1e-6f);
#pragma unroll
    for (int j = 0; j < 3; j++) {
        int i = tid + j * 512;
        sq[i] = qv[j] * rq * qs[i];
        sk[i] = kv[j] * rk * ks[i];
    }
    __syncthreads();
#pragma unroll
    for (int j = 0; j < 3; j++) {
        int i = tid + j * 512;
        int h = i >> 7, d = i & 127;
        int jj = d & 63;
        float cv = cs_tab[jj], sv = sn_tab[jj];
        int base = h * HD;
        float qo, ko;
        if (d < 64) {
            qo = sq[base + d] * cv - sq[base + d + 64] * sv;
            ko = sk[base + d] * cv - sk[base + d + 64] * sv;
        } else {
            qo = sq[base + d] * cv + sq[base + d - 64] * sv;
            ko = sk[base + d] * cv + sk[base + d - 64] * sv;
        }
        size_t o = ((size_t)(b * NHEAD + h) * NTOK + t) * HD + d;
        Q[o] = qo; K[o] = ko; V[o] = vv[j];
    }
}

// ------------------------- flash attention fp32 + FFMA2, BQ=BK=128 -------
// 256 threads, 16x16 grid, 8x8 microtile, packed f32x2 FMA throughout.
// smem: Qt[128][128] swizzled, Kt[128][128] swizzled (aliased by P[128][132]),
//       Vs[128][132].  Total 200704 bytes -> 1 block/SM.
__global__ __launch_bounds__(256, 1) void attn2_k(
    const float* __restrict__ Q, const float* __restrict__ K,
    const float* __restrict__ V, float* __restrict__ O)
{
    extern __shared__ float smx[];
    float* Qt = smx;                       // 16384 floats
    float* Kt = smx + 16384;               // 16896 floats region (Kt or P)
    float* Ps = Kt;
    float* Vs = smx + 16384 + 16896;       // 16896 floats

    int tid = threadIdx.x;
    int qt = blockIdx.x, bh = blockIdx.y;
    int b = bh / NHEAD, h = bh - b * NHEAD;
    const float* Qb = Q + ((size_t)bh * NTOK + qt * 128) * HD;
    const float* Kb = K + (size_t)bh * NTOK * HD;
    const float* Vb = V + (size_t)bh * NTOK * HD;

    int ty = tid >> 4, tx = tid & 15;

    // ---- transpose Q (128 tokens x 128 d) into Qt[d][tok ^ swz(d)] ----
#pragma unroll
    for (int i = 0; i < 16; i++) {
        int f = tid + i * 256;
        int r = f >> 5;               // token row 0..127
        int c4 = (f & 31) * 4;        // d base
        float4 qv = *(const float4*)&Qb[r * HD + c4];
        int cs = r ^ (((c4 >> 2) & 7) << 2);
        Qt[(c4 + 0) * 128 + cs] = qv.x;
        Qt[(c4 + 1) * 128 + cs] = qv.y;
        Qt[(c4 + 2) * 128 + cs] = qv.z;
        Qt[(c4 + 3) * 128 + cs] = qv.w;
    }

    float m[8], l[8];
    unsigned long long o2[8][4];
#pragma unroll
    for (int i = 0; i < 8; i++) {
        m[i] = -INFINITY; l[i] = 0.f;
#pragma unroll
        for (int j = 0; j < 4; j++) o2[i][j] = 0ull;
    }

    for (int kt = 0; kt < 18; kt++) {
        __syncthreads();   // Qt ready (iter 0) / prev P,Vs fully consumed

        // ---- load K (transposed+swizzled) and V ----
#pragma unroll
        for (int i = 0; i < 16; i++) {
            int f = tid + i * 256;
            int r = f >> 5, c4 = (f & 31) * 4;
            const float* kp = &Kb[((size_t)(kt * 128 + r)) * HD + c4];
            float4 kv = *(const float4*)kp;
            int cs = r ^ (((c4 >> 2) & 7) << 2);
            Kt[(c4 + 0) * 128 + cs] = kv.x;
            Kt[(c4 + 1) * 128 + cs] = kv.y;
            Kt[(c4 + 2) * 128 + cs] = kv.z;
            Kt[(c4 + 3) * 128 + cs] = kv.w;
            *(float4*)&Vs[r * 132 + c4] =
                *(const float4*)&Vb[((size_t)(kt * 128 + r)) * HD + c4];
        }
        __syncthreads();

        // ---- S = Q K^T via FFMA2 outer products ----
        unsigned long long acc[8][4];
#pragma unroll
        for (int i = 0; i < 8; i++)
#pragma unroll
            for (int j = 0; j < 4; j++) acc[i][j] = 0ull;

#pragma unroll 4
        for (int kk = 0; kk < 128; kk++) {
            int fq = ((kk >> 2) & 7) << 2;
            const float* qrow = Qt + kk * 128;
            const float* krow = Kt + kk * 128;
            float4 qa0 = *(const float4*)&qrow[(ty * 8) ^ fq];
            float4 qa1 = *(const float4*)&qrow[(ty * 8 + 4) ^ fq];
            ulonglong2 kb0 = *(const ulonglong2*)&krow[(tx * 8) ^ fq];
            ulonglong2 kb1 = *(const ulonglong2*)&krow[(tx * 8 + 4) ^ fq];
            unsigned long long bb0 = kb0.x, bb1 = kb0.y, bb2 = kb1.x, bb3 = kb1.y;
            float qa[8] = {qa0.x, qa0.y, qa0.z, qa0.w, qa1.x, qa1.y, qa1.z, qa1.w};
#pragma unroll
            for (int i = 0; i < 8; i++) {
                unsigned long long a2 = bcast2(qa[i]);
                acc[i][0] = ffma2(a2, bb0, acc[i][0]);
                acc[i][1] = ffma2(a2, bb1, acc[i][1]);
                acc[i][2] = ffma2(a2, bb2, acc[i][2]);
                acc[i][3] = ffma2(a2, bb3, acc[i][3]);
            }
        }

        // ---- online softmax (registers) ----
        const float sc = 0.08838834764831845f;  // 1/sqrt(128)
        float al[8];
#pragma unroll
        for (int i = 0; i < 8; i++) {
            float s[8];
#pragma unroll
            for (int j = 0; j < 4; j++) {
                float2 v = *(float2*)&acc[i][j];
                s[2 * j] = v.x * sc; s[2 * j + 1] = v.y * sc;
            }
            float mx = s[0];
#pragma unroll
            for (int j = 1; j < 8; j++) mx = fmaxf(mx, s[j]);
#pragma unroll
            for (int msk = 8; msk; msk >>= 1)
                mx = fmaxf(mx, __shfl_xor_sync(0xffffffffu, mx, msk));
            float mn = fmaxf(m[i], mx);
            al[i] = __expf(m[i] - mn);
            m[i] = mn;
            float rs = 0.f;
#pragma unroll
            for (int j = 0; j < 8; j++) { s[j] = __expf(s[j] - mn); rs += s[j]; }
#pragma unroll
            for (int msk = 8; msk; msk >>= 1)
                rs += __shfl_xor_sync(0xffffffffu, rs, msk);
            l[i] = l[i] * al[i] + rs;
            // stash exp'd values back into acc registers
#pragma unroll
            for (int j = 0; j < 4; j++)
                *(float2*)&acc[i][j] = make_float2(s[2 * j], s[2 * j + 1]);
        }

        __syncthreads();   // all warps done reading Kt -> safe to alias as P

        // ---- write P, rescale O ----
#pragma unroll
        for (int i = 0; i < 8; i++) {
            int r = ty * 8 + i;
            float2 p0 = *(float2*)&acc[i][0];
            float2 p1 = *(float2*)&acc[i][1];
            float2 p2 = *(float2*)&acc[i][2];
            float2 p3 = *(float2*)&acc[i][3];
            *(float4*)&Ps[r * 132 + tx * 8]     = make_float4(p0.x, p0.y, p1.x, p1.y);
            *(float4*)&Ps[r * 132 + tx * 8 + 4] = make_float4(p2.x, p2.y, p3.x, p3.y);
            unsigned long long a2 = bcast2(al[i]);
#pragma unroll
            for (int j = 0; j < 4; j++) o2[i][j] = fmul2(o2[i][j], a2);
        }
        __syncthreads();

        // ---- O += P V via FFMA2 ----
#pragma unroll 2
        for (int k0 = 0; k0 < 128; k0 += 4) {
            float4 pr[8];
#pragma unroll
            for (int i = 0; i < 8; i++)
                pr[i] = *(const float4*)&Ps[(ty * 8 + i) * 132 + k0];
#pragma unroll
            for (int kj = 0; kj < 4; kj++) {
                const float* vrow = Vs + (k0 + kj) * 132 + tx * 8;
                ulonglong2 v0 = *(const ulonglong2*)&vrow[0];
                ulonglong2 v1 = *(const ulonglong2*)&vrow[4];
                unsigned long long vb0 = v0.x, vb1 = v0.y, vb2 = v1.x, vb3 = v1.y;
#pragma unroll
                for (int i = 0; i < 8; i++) {
                    float p = (kj == 0) ? pr[i].x : (kj == 1) ? pr[i].y
                            : (kj == 2) ? pr[i].z : pr[i].w;
                    unsigned long long a2 = bcast2(p);
                    o2[i][0] = ffma2(a2, vb0, o2[i][0]);
                    o2[i][1] = ffma2(a2, vb1, o2[i][1]);
                    o2[i][2] = ffma2(a2, vb2, o2[i][2]);
                    o2[i][3] = ffma2(a2, vb3, o2[i][3]);
                }
            }
        }
    }

    // ---- epilogue ----
#pragma unroll
    for (int i = 0; i < 8; i++) {
        float inv = 1.0f / l[i];
        int token = qt * 128 + ty * 8 + i;
        float* op = O + ((size_t)(b * NTOK + token)) * DMODEL + h * HD + tx * 8;
        float2 r0 = *(float2*)&o2[i][0];
        float2 r1 = *(float2*)&o2[i][1];
        float2 r2 = *(float2*)&o2[i][2];
        float2 r3 = *(float2*)&o2[i][3];
        float4 w0 = make_float4(r0.x * inv, r0.y * inv, r1.x * inv, r1.y * inv);
        float4 w1 = make_float4(r2.x * inv, r2.y * inv, r3.x * inv, r3.y * inv);
        *(float4*)&op[0] = w0;
        *(float4*)&op[4] = w1;
    }
}

// ------------------------- launch -----------------------------------------
extern "C" void kernel_launch(void* const* d_in, const int* in_sizes, int n_in,
                              void* d_out, int out_size)
{
    const float* input   = (const float*)d_in[0];
    const float* context = (const float*)d_in[1];
    const float* Wqi = (const float*)d_in[2];
    const float* bqi = (const float*)d_in[3];
    const float* Wqc = (const float*)d_in[4];
    const float* bqc = (const float*)d_in[5];
    const float* qsi = (const float*)d_in[6];
    const float* ksi = (const float*)d_in[7];
    const float* qsc = (const float*)d_in[8];
    const float* ksc = (const float*)d_in[9];
    const float* Woi = (const float*)d_in[10];
    const float* boi = (const float*)d_in[11];
    const float* Woc = (const float*)d_in[12];
    const float* boc = (const float*)d_in[13];
    float* out = (float*)d_out;

    float *qkv, *q, *k, *v, *o;
    cudaGetSymbolAddress((void**)&qkv, g_qkv);
    cudaGetSymbolAddress((void**)&q,   g_q);
    cudaGetSymbolAddress((void**)&k,   g_k);
    cudaGetSymbolAddress((void**)&v,   g_v);
    cudaGetSymbolAddress((void**)&o,   g_o);

    const int BIG = 1 << 30;

    // QKV projections
    sgemm_tc<<<dim3(36, 32), 256>>>(input, Wqi, bqi, qkv,
                                    4096, 4608, 1536,
                                    BIG, 0, 0,
                                    SINP, SCTX, NTOK, 4608);
    sgemm_tc<<<dim3(36, 4), 256>>>(context, Wqc, bqc, qkv,
                                   512, 4608, 1536,
                                   BIG, 0, 0,
                                   SCTX, 0, NTOK, 4608);

    // RMSNorm + RoPE + transpose
    norm_rope_k<<<NB * NTOK, 512>>>(qkv, qsi, ksi, qsc, ksc, q, k, v);

    // attention (FFMA2 path)
    cudaFuncSetAttribute(attn2_k, cudaFuncAttributeMaxDynamicSharedMemorySize, 200704);
    attn2_k<<<dim3(18, NB * NHEAD), 256, 200704>>>(q, k, v, o);

    // output projections
    sgemm_tc<<<dim3(12, 32), 256>>>(o, Woi, boi, out,
                                    4096, 1536, 1536,
                                    SINP, SCTX, NTOK,
                                    BIG, 0, 0, 1536);
    sgemm_tc<<<dim3(12, 4), 256>>>(o, Woc, boc, out + (size_t)NB * SINP * DMODEL,
                                   512, 1536, 1536,
                                   SCTX, 0, NTOK,
                                   BIG, 0, 0, 1536);
}

// round 5
// speedup vs baseline: 2.6110x; 1.4648x over previous
#include <cuda_runtime.h>
#include <math.h>

#define NHEAD 12
#define HD    128
#define DMODEL 1536
#define SCTX  256
#define SINP  2048
#define NTOK  2304
#define NB    2

// ------------------------- scratch (device globals; no allocs allowed) ----
__device__ float g_qkv[(size_t)NB * NTOK * 3 * DMODEL];
__device__ float g_q[(size_t)NB * NHEAD * NTOK * HD];     // [b*h][tok][128]
__device__ float g_k[(size_t)NB * NHEAD * NTOK * HD];
__device__ float g_v[(size_t)NB * NHEAD * NTOK * HD];
__device__ float g_vt[(size_t)NB * NHEAD * HD * NTOK];    // [b*h][d][tok] (tf32-rounded)
__device__ float g_o[(size_t)NB * NTOK * DMODEL];

// row map: r(m) = (m/S)*Stride + Off + m%S   (S=1<<30 -> identity)
__device__ __forceinline__ int maprow(int m, int S, int off, int st) {
    return (m / S) * st + off + (m % S);
}

__device__ __forceinline__ float tf32_rn(float x) {
    unsigned r;
    asm("cvt.rna.tf32.f32 %0, %1;" : "=r"(r) : "f"(x));
    return __uint_as_float(r);
}

__device__ __forceinline__ void mma_tf32(float* d, const unsigned* a, const unsigned* b) {
    asm volatile(
        "mma.sync.aligned.m16n8k8.row.col.f32.tf32.tf32.f32 "
        "{%0,%1,%2,%3},{%4,%5,%6,%7},{%8,%9},{%0,%1,%2,%3};"
        : "+f"(d[0]), "+f"(d[1]), "+f"(d[2]), "+f"(d[3])
        : "r"(a[0]), "r"(a[1]), "r"(a[2]), "r"(a[3]), "r"(b[0]), "r"(b[1]));
}

// ------------------------- tf32 GEMM, split-A (2-term) for accuracy -------
// C[crow(m)][bn+*] = A[arow(m)][:] @ B[:, bn+*] + bias
__global__ __launch_bounds__(256, 2) void sgemm_tc(
    const float* __restrict__ A, const float* __restrict__ Bm,
    const float* __restrict__ bias, float* __restrict__ C,
    int M, int N, int K,
    int aS, int aOff, int aStride,
    int cS, int cOff, int cStride, int ldc)
{
    __shared__ float As[2][16][128];   // raw fp32, [k][m ^ ((k&3)<<3)]
    __shared__ float Bs[2][16][136];   // tf32-rounded

    int tid = threadIdx.x;
    int bm = blockIdx.y * 128, bn = blockIdx.x * 128;

    int arow = tid >> 2;
    int kseg = tid & 3;
    const float* aptr0 = A + (size_t)maprow(bm + arow,      aS, aOff, aStride) * K + kseg;
    const float* aptr1 = A + (size_t)maprow(bm + arow + 64, aS, aOff, aStride) * K + kseg;
    int brow = tid >> 5;
    int bcol = (tid & 31) * 4;
    const float* bptr = Bm + (size_t)brow * N + bn + bcol;

    int warp = tid >> 5;
    int wm = warp & 3, wn = warp >> 2;
    int lane = tid & 31;
    int lg = lane >> 2, lt = lane & 3;

    float acc[2][8][4];
#pragma unroll
    for (int mi = 0; mi < 2; mi++)
#pragma unroll
        for (int nf = 0; nf < 8; nf++)
#pragma unroll
            for (int r = 0; r < 4; r++) acc[mi][nf][r] = 0.f;

    int ntiles = K / 16;

    float ra0[4], ra1[4];
    float4 rb0, rb1;

#pragma unroll
    for (int i = 0; i < 4; i++) { ra0[i] = aptr0[4 * i]; ra1[i] = aptr1[4 * i]; }
    rb0 = *(const float4*)(bptr);
    rb1 = *(const float4*)(bptr + (size_t)8 * N);
#pragma unroll
    for (int i = 0; i < 4; i++) {
        As[0][kseg + 4 * i][arow        ^ (kseg << 3)] = ra0[i];
        As[0][kseg + 4 * i][(arow + 64) ^ (kseg << 3)] = ra1[i];
    }
    {
        float4 c0 = make_float4(tf32_rn(rb0.x), tf32_rn(rb0.y), tf32_rn(rb0.z), tf32_rn(rb0.w));
        float4 c1 = make_float4(tf32_rn(rb1.x), tf32_rn(rb1.y), tf32_rn(rb1.z), tf32_rn(rb1.w));
        *(float4*)&Bs[0][brow][bcol]     = c0;
        *(float4*)&Bs[0][brow + 8][bcol] = c1;
    }
    __syncthreads();

    for (int t = 0; t < ntiles; t++) {
        int cur = t & 1;
        if (t + 1 < ntiles) {
            const float* a0 = aptr0 + (size_t)(t + 1) * 16;
            const float* a1 = aptr1 + (size_t)(t + 1) * 16;
#pragma unroll
            for (int i = 0; i < 4; i++) { ra0[i] = a0[4 * i]; ra1[i] = a1[4 * i]; }
            const float* bp = bptr + (size_t)(t + 1) * 16 * N;
            rb0 = *(const float4*)(bp);
            rb1 = *(const float4*)(bp + (size_t)8 * N);
        }

#pragma unroll
        for (int kf = 0; kf < 2; kf++) {
            int kb = kf * 8;
            unsigned ah[2][4], al2[2][4];
#pragma unroll
            for (int mi = 0; mi < 2; mi++) {
                int m0 = wm * 32 + mi * 16 + lg;
                float x0 = As[cur][kb + lt]    [m0       ^ (lt << 3)];
                float x1 = As[cur][kb + lt]    [(m0 + 8) ^ (lt << 3)];
                float x2 = As[cur][kb + lt + 4][m0       ^ (lt << 3)];
                float x3 = As[cur][kb + lt + 4][(m0 + 8) ^ (lt << 3)];
                float h0 = tf32_rn(x0), h1 = tf32_rn(x1), h2 = tf32_rn(x2), h3 = tf32_rn(x3);
                ah[mi][0] = __float_as_uint(h0); al2[mi][0] = __float_as_uint(tf32_rn(x0 - h0));
                ah[mi][1] = __float_as_uint(h1); al2[mi][1] = __float_as_uint(tf32_rn(x1 - h1));
                ah[mi][2] = __float_as_uint(h2); al2[mi][2] = __float_as_uint(tf32_rn(x2 - h2));
                ah[mi][3] = __float_as_uint(h3); al2[mi][3] = __float_as_uint(tf32_rn(x3 - h3));
            }
            unsigned bf[8][2];
#pragma unroll
            for (int nf = 0; nf < 8; nf++) {
                int n = wn * 64 + nf * 8 + lg;
                bf[nf][0] = __float_as_uint(Bs[cur][kb + lt][n]);
                bf[nf][1] = __float_as_uint(Bs[cur][kb + lt + 4][n]);
            }
#pragma unroll
            for (int mi = 0; mi < 2; mi++)
#pragma unroll
                for (int nf = 0; nf < 8; nf++)
                    mma_tf32(acc[mi][nf], ah[mi], bf[nf]);
#pragma unroll
            for (int mi = 0; mi < 2; mi++)
#pragma unroll
                for (int nf = 0; nf < 8; nf++)
                    mma_tf32(acc[mi][nf], al2[mi], bf[nf]);
        }

        if (t + 1 < ntiles) {
            int alt = cur ^ 1;
#pragma unroll
            for (int i = 0; i < 4; i++) {
                As[alt][kseg + 4 * i][arow        ^ (kseg << 3)] = ra0[i];
                As[alt][kseg + 4 * i][(arow + 64) ^ (kseg << 3)] = ra1[i];
            }
            float4 c0 = make_float4(tf32_rn(rb0.x), tf32_rn(rb0.y), tf32_rn(rb0.z), tf32_rn(rb0.w));
            float4 c1 = make_float4(tf32_rn(rb1.x), tf32_rn(rb1.y), tf32_rn(rb1.z), tf32_rn(rb1.w));
            *(float4*)&Bs[alt][brow][bcol]     = c0;
            *(float4*)&Bs[alt][brow + 8][bcol] = c1;
        }
        __syncthreads();
    }

#pragma unroll
    for (int mi = 0; mi < 2; mi++) {
        int r0 = bm + wm * 32 + mi * 16 + lg;
        int cr0 = maprow(r0,     cS, cOff, cStride);
        int cr1 = maprow(r0 + 8, cS, cOff, cStride);
#pragma unroll
        for (int nf = 0; nf < 8; nf++) {
            int cn = bn + wn * 64 + nf * 8 + 2 * lt;
            float b0 = bias[cn], b1 = bias[cn + 1];
            float2 v0 = make_float2(acc[mi][nf][0] + b0, acc[mi][nf][1] + b1);
            float2 v1 = make_float2(acc[mi][nf][2] + b0, acc[mi][nf][3] + b1);
            *(float2*)&C[(size_t)cr0 * ldc + cn] = v0;
            *(float2*)&C[(size_t)cr1 * ldc + cn] = v1;
        }
    }
}

// ------------------------- fused RMSNorm + RoPE + head transpose ----------
__global__ __launch_bounds__(512) void norm_rope_k(
    const float* __restrict__ qkv,
    const float* __restrict__ qs_in, const float* __restrict__ ks_in,
    const float* __restrict__ qs_ctx, const float* __restrict__ ks_ctx,
    float* __restrict__ Q, float* __restrict__ K, float* __restrict__ V)
{
    __shared__ float sq[DMODEL], sk[DMODEL];
    __shared__ float cs_tab[64], sn_tab[64];
    __shared__ float wq[16], wk[16], ssum[2];

    int bt = blockIdx.x;
    int b = bt / NTOK, t = bt - b * NTOK;
    const float* row = qkv + (size_t)bt * (3 * DMODEL);
    bool is_ctx = (t < SCTX);
    const float* qs = is_ctx ? qs_ctx : qs_in;
    const float* ks = is_ctx ? ks_ctx : ks_in;
    int tid = threadIdx.x;

    if (tid < 64) {
        float invf = (float)pow(10000.0, -(double)tid / 64.0);
        float ang = (float)t * invf;
        cs_tab[tid] = (float)cos((double)ang);
        sn_tab[tid] = (float)sin((double)ang);
    }

    float aq = 0.f, ak = 0.f;
    float qv[3], kv[3], vv[3];
#pragma unroll
    for (int j = 0; j < 3; j++) {
        int i = tid + j * 512;
        qv[j] = row[i];
        kv[j] = row[DMODEL + i];
        vv[j] = row[2 * DMODEL + i];
        aq += qv[j] * qv[j];
        ak += kv[j] * kv[j];
    }
#pragma unroll
    for (int off = 16; off; off >>= 1) {
        aq += __shfl_xor_sync(0xffffffffu, aq, off);
        ak += __shfl_xor_sync(0xffffffffu, ak, off);
    }
    int wid = tid >> 5, lane = tid & 31;
    if (!lane) { wq[wid] = aq; wk[wid] = ak; }
    __syncthreads();
    if (tid == 0) {
        float s1 = 0.f, s2 = 0.f;
#pragma unroll
        for (int w = 0; w < 16; w++) { s1 += wq[w]; s2 += wk[w]; }
        ssum[0] = s1; ssum[1] = s2;
    }
    __syncthreads();
    float rq = rsqrtf(ssum[0] * (1.0f / DMODEL) + 1e-6f);
    float rk = rsqrtf(ssum[1] * (1.0f / DMODEL) + 1e-6f);
#pragma unroll
    for (int j = 0; j < 3; j++) {
        int i = tid + j * 512;
        sq[i] = qv[j] * rq * qs[i];
        sk[i] = kv[j] * rk * ks[i];
    }
    __syncthreads();
#pragma unroll
    for (int j = 0; j < 3; j++) {
        int i = tid + j * 512;
        int h = i >> 7, d = i & 127;
        int jj = d & 63;
        float cv = cs_tab[jj], sv = sn_tab[jj];
        int base = h * HD;
        float qo, ko;
        if (d < 64) {
            qo = sq[base + d] * cv - sq[base + d + 64] * sv;
            ko = sk[base + d] * cv - sk[base + d + 64] * sv;
        } else {
            qo = sq[base + d] * cv + sq[base + d - 64] * sv;
            ko = sk[base + d] * cv + sk[base + d - 64] * sv;
        }
        size_t o = ((size_t)(b * NHEAD + h) * NTOK + t) * HD + d;
        Q[o] = qo; K[o] = ko; V[o] = vv[j];
    }
}

// ------------------------- V transpose: [bh][tok][d] -> [bh][d][tok] ------
__global__ __launch_bounds__(256) void transpose_v(
    const float* __restrict__ V, float* __restrict__ Vt)
{
    __shared__ float tile[32][33];
    int bh = blockIdx.z;
    int t0 = blockIdx.x * 32, d0 = blockIdx.y * 32;
    int tx = threadIdx.x, ty = threadIdx.y;   // 32 x 8
    const float* src = V + ((size_t)bh * NTOK + t0) * HD + d0;
#pragma unroll
    for (int i = 0; i < 4; i++)
        tile[ty + 8 * i][tx] = src[(ty + 8 * i) * HD + tx];
    __syncthreads();
    float* dst = Vt + ((size_t)bh * HD + d0) * NTOK + t0;
#pragma unroll
    for (int i = 0; i < 4; i++)
        dst[(ty + 8 * i) * NTOK + tx] = tf32_rn(tile[tx][ty + 8 * i]);
}

// ------------------------- tf32 tensor-core flash attention ---------------
// BQ=BK=128, 256 threads, warp grid 4(m)x2(n), warp tile 32x64.
// smem: Qs[128][132], Ks[128][132] (aliased by Ps), Vs[128][132] (rows=d),
//       red[2][128][2].  All fragment LDS.32 conflict-free via pad 132.
#define ALD 132
__global__ __launch_bounds__(256, 1) void attn3_k(
    const float* __restrict__ Q, const float* __restrict__ K,
    const float* __restrict__ Vt, float* __restrict__ O)
{
    extern __shared__ float smx[];
    float* Qs = smx;
    float* Ks = smx + 128 * ALD;
    float* Ps = Ks;
    float* Vs = smx + 2 * 128 * ALD;
    float* red = smx + 3 * 128 * ALD;   // [2][128][2]

    int tid = threadIdx.x;
    int warp = tid >> 5, lane = tid & 31;
    int wm = warp & 3, wn = warp >> 2;
    int lg = lane >> 2, lt = lane & 3;

    int qt = blockIdx.x, bh = blockIdx.y;
    int b = bh / NHEAD, h = bh - b * NHEAD;
    const float* Qb = Q + ((size_t)bh * NTOK + qt * 128) * HD;
    const float* Kb = K + (size_t)bh * NTOK * HD;
    const float* Vtb = Vt + (size_t)bh * HD * NTOK;

    // fill Q (tf32-rounded)
#pragma unroll
    for (int i = 0; i < 16; i++) {
        int f = tid + i * 256;
        int r = f >> 5, c4 = (f & 31) * 4;
        float4 v = *(const float4*)&Qb[r * HD + c4];
        *(float4*)&Qs[r * ALD + c4] =
            make_float4(tf32_rn(v.x), tf32_rn(v.y), tf32_rn(v.z), tf32_rn(v.w));
    }

    float m[2][2], l[2][2];
    float oacc[2][8][4];
#pragma unroll
    for (int mi = 0; mi < 2; mi++) {
        m[mi][0] = -INFINITY; m[mi][1] = -INFINITY;
        l[mi][0] = 0.f; l[mi][1] = 0.f;
#pragma unroll
        for (int nf = 0; nf < 8; nf++)
#pragma unroll
            for (int r = 0; r < 4; r++) oacc[mi][nf][r] = 0.f;
    }

    const float sc = 0.08838834764831845f;  // 1/sqrt(128)

    for (int kt = 0; kt < 18; kt++) {
        __syncthreads();   // prev PV reads done; Q visible on iter 0

        // fill K tile [tok][d] and V tile [d][tok]
#pragma unroll
        for (int i = 0; i < 16; i++) {
            int f = tid + i * 256;
            int r = f >> 5, c4 = (f & 31) * 4;
            float4 kv = *(const float4*)&Kb[((size_t)(kt * 128 + r)) * HD + c4];
            *(float4*)&Ks[r * ALD + c4] =
                make_float4(tf32_rn(kv.x), tf32_rn(kv.y), tf32_rn(kv.z), tf32_rn(kv.w));
            *(float4*)&Vs[r * ALD + c4] =
                *(const float4*)&Vtb[(size_t)r * NTOK + kt * 128 + c4];
        }
        __syncthreads();

        // ---- S = Q K^T ----
        float sacc[2][8][4];
#pragma unroll
        for (int mi = 0; mi < 2; mi++)
#pragma unroll
            for (int nf = 0; nf < 8; nf++)
#pragma unroll
                for (int r = 0; r < 4; r++) sacc[mi][nf][r] = 0.f;

#pragma unroll
        for (int ks = 0; ks < 16; ks++) {
            int k = ks * 8;
            unsigned aq[2][4];
#pragma unroll
            for (int mi = 0; mi < 2; mi++) {
                int R = wm * 32 + mi * 16 + lg;
                aq[mi][0] = __float_as_uint(Qs[R * ALD + k + lt]);
                aq[mi][1] = __float_as_uint(Qs[(R + 8) * ALD + k + lt]);
                aq[mi][2] = __float_as_uint(Qs[R * ALD + k + lt + 4]);
                aq[mi][3] = __float_as_uint(Qs[(R + 8) * ALD + k + lt + 4]);
            }
            unsigned bk[8][2];
#pragma unroll
            for (int nf = 0; nf < 8; nf++) {
                int n = wn * 64 + nf * 8 + lg;
                bk[nf][0] = __float_as_uint(Ks[n * ALD + k + lt]);
                bk[nf][1] = __float_as_uint(Ks[n * ALD + k + lt + 4]);
            }
#pragma unroll
            for (int mi = 0; mi < 2; mi++)
#pragma unroll
                for (int nf = 0; nf < 8; nf++)
                    mma_tf32(sacc[mi][nf], aq[mi], bk[nf]);
        }

        // ---- warp-local row max, write partials ----
#pragma unroll
        for (int mi = 0; mi < 2; mi++) {
            int row0 = wm * 32 + mi * 16 + lg;
            float mx0 = -INFINITY, mx1 = -INFINITY;
#pragma unroll
            for (int nf = 0; nf < 8; nf++) {
                sacc[mi][nf][0] *= sc; sacc[mi][nf][1] *= sc;
                sacc[mi][nf][2] *= sc; sacc[mi][nf][3] *= sc;
                mx0 = fmaxf(mx0, fmaxf(sacc[mi][nf][0], sacc[mi][nf][1]));
                mx1 = fmaxf(mx1, fmaxf(sacc[mi][nf][2], sacc[mi][nf][3]));
            }
            mx0 = fmaxf(mx0, __shfl_xor_sync(0xffffffffu, mx0, 1));
            mx0 = fmaxf(mx0, __shfl_xor_sync(0xffffffffu, mx0, 2));
            mx1 = fmaxf(mx1, __shfl_xor_sync(0xffffffffu, mx1, 1));
            mx1 = fmaxf(mx1, __shfl_xor_sync(0xffffffffu, mx1, 2));
            if (lt == 0) {
                red[row0 * 2 + wn] = mx0;
                red[(row0 + 8) * 2 + wn] = mx1;
            }
        }
        __syncthreads();   // maxes visible; all Ks reads done -> Ps safe

        // ---- softmax: exp, write P (tf32), partial sums, rescale O ----
        float alpha[2][2];
#pragma unroll
        for (int mi = 0; mi < 2; mi++) {
            int row0 = wm * 32 + mi * 16 + lg;
            float gm0 = fmaxf(red[row0 * 2], red[row0 * 2 + 1]);
            float gm1 = fmaxf(red[(row0 + 8) * 2], red[(row0 + 8) * 2 + 1]);
            float mn0 = fmaxf(m[mi][0], gm0), mn1 = fmaxf(m[mi][1], gm1);
            alpha[mi][0] = __expf(m[mi][0] - mn0);
            alpha[mi][1] = __expf(m[mi][1] - mn1);
            m[mi][0] = mn0; m[mi][1] = mn1;
            float rs0 = 0.f, rs1 = 0.f;
#pragma unroll
            for (int nf = 0; nf < 8; nf++) {
                float p0 = tf32_rn(__expf(sacc[mi][nf][0] - mn0));
                float p1 = tf32_rn(__expf(sacc[mi][nf][1] - mn0));
                float p2 = tf32_rn(__expf(sacc[mi][nf][2] - mn1));
                float p3 = tf32_rn(__expf(sacc[mi][nf][3] - mn1));
                rs0 += p0 + p1; rs1 += p2 + p3;
                int col = wn * 64 + nf * 8 + 2 * lt;
                *(float2*)&Ps[row0 * ALD + col] = make_float2(p0, p1);
                *(float2*)&Ps[(row0 + 8) * ALD + col] = make_float2(p2, p3);
                oacc[mi][nf][0] *= alpha[mi][0];
                oacc[mi][nf][1] *= alpha[mi][0];
                oacc[mi][nf][2] *= alpha[mi][1];
                oacc[mi][nf][3] *= alpha[mi][1];
            }
            rs0 += __shfl_xor_sync(0xffffffffu, rs0, 1);
            rs0 += __shfl_xor_sync(0xffffffffu, rs0, 2);
            rs1 += __shfl_xor_sync(0xffffffffu, rs1, 1);
            rs1 += __shfl_xor_sync(0xffffffffu, rs1, 2);
            if (lt == 0) {
                red[256 + row0 * 2 + wn] = rs0;
                red[256 + (row0 + 8) * 2 + wn] = rs1;
            }
        }
        __syncthreads();   // Ps + sums visible

#pragma unroll
        for (int mi = 0; mi < 2; mi++) {
            int row0 = wm * 32 + mi * 16 + lg;
            l[mi][0] = l[mi][0] * alpha[mi][0]
                     + red[256 + row0 * 2] + red[256 + row0 * 2 + 1];
            l[mi][1] = l[mi][1] * alpha[mi][1]
                     + red[256 + (row0 + 8) * 2] + red[256 + (row0 + 8) * 2 + 1];
        }

        // ---- O += P V ----
#pragma unroll
        for (int ks = 0; ks < 16; ks++) {
            int k = ks * 8;
            unsigned ap[2][4];
#pragma unroll
            for (int mi = 0; mi < 2; mi++) {
                int R = wm * 32 + mi * 16 + lg;
                ap[mi][0] = __float_as_uint(Ps[R * ALD + k + lt]);
                ap[mi][1] = __float_as_uint(Ps[(R + 8) * ALD + k + lt]);
                ap[mi][2] = __float_as_uint(Ps[R * ALD + k + lt + 4]);
                ap[mi][3] = __float_as_uint(Ps[(R + 8) * ALD + k + lt + 4]);
            }
            unsigned bv[8][2];
#pragma unroll
            for (int nf = 0; nf < 8; nf++) {
                int n = wn * 64 + nf * 8 + lg;   // n = d
                bv[nf][0] = __float_as_uint(Vs[n * ALD + k + lt]);
                bv[nf][1] = __float_as_uint(Vs[n * ALD + k + lt + 4]);
            }
#pragma unroll
            for (int mi = 0; mi < 2; mi++)
#pragma unroll
                for (int nf = 0; nf < 8; nf++)
                    mma_tf32(oacc[mi][nf], ap[mi], bv[nf]);
        }
    }

    // ---- epilogue ----
#pragma unroll
    for (int mi = 0; mi < 2; mi++) {
        int row0 = wm * 32 + mi * 16 + lg;
        float inv0 = 1.0f / l[mi][0], inv1 = 1.0f / l[mi][1];
        size_t base0 = ((size_t)(b * NTOK + qt * 128 + row0)) * DMODEL + h * HD;
        size_t base1 = ((size_t)(b * NTOK + qt * 128 + row0 + 8)) * DMODEL + h * HD;
#pragma unroll
        for (int nf = 0; nf < 8; nf++) {
            int col = wn * 64 + nf * 8 + 2 * lt;
            *(float2*)&O[base0 + col] =
                make_float2(oacc[mi][nf][0] * inv0, oacc[mi][nf][1] * inv0);
            *(float2*)&O[base1 + col] =
                make_float2(oacc[mi][nf][2] * inv1, oacc[mi][nf][3] * inv1);
        }
    }
}

// ------------------------- launch -----------------------------------------
extern "C" void kernel_launch(void* const* d_in, const int* in_sizes, int n_in,
                              void* d_out, int out_size)
{
    const float* input   = (const float*)d_in[0];
    const float* context = (const float*)d_in[1];
    const float* Wqi = (const float*)d_in[2];
    const float* bqi = (const float*)d_in[3];
    const float* Wqc = (const float*)d_in[4];
    const float* bqc = (const float*)d_in[5];
    const float* qsi = (const float*)d_in[6];
    const float* ksi = (const float*)d_in[7];
    const float* qsc = (const float*)d_in[8];
    const float* ksc = (const float*)d_in[9];
    const float* Woi = (const float*)d_in[10];
    const float* boi = (const float*)d_in[11];
    const float* Woc = (const float*)d_in[12];
    const float* boc = (const float*)d_in[13];
    float* out = (float*)d_out;

    float *qkv, *q, *k, *v, *vt, *o;
    cudaGetSymbolAddress((void**)&qkv, g_qkv);
    cudaGetSymbolAddress((void**)&q,   g_q);
    cudaGetSymbolAddress((void**)&k,   g_k);
    cudaGetSymbolAddress((void**)&v,   g_v);
    cudaGetSymbolAddress((void**)&vt,  g_vt);
    cudaGetSymbolAddress((void**)&o,   g_o);

    const int BIG = 1 << 30;

    // QKV projections
    sgemm_tc<<<dim3(36, 32), 256>>>(input, Wqi, bqi, qkv,
                                    4096, 4608, 1536,
                                    BIG, 0, 0,
                                    SINP, SCTX, NTOK, 4608);
    sgemm_tc<<<dim3(36, 4), 256>>>(context, Wqc, bqc, qkv,
                                   512, 4608, 1536,
                                   BIG, 0, 0,
                                   SCTX, 0, NTOK, 4608);

    // RMSNorm + RoPE + transpose
    norm_rope_k<<<NB * NTOK, 512>>>(qkv, qsi, ksi, qsc, ksc, q, k, v);

    // V transpose (tf32-rounded) for the tensor-core PV GEMM
    transpose_v<<<dim3(NTOK / 32, HD / 32, NB * NHEAD), dim3(32, 8)>>>(v, vt);

    // tensor-core attention
    int smem = (3 * 128 * ALD + 512) * 4;
    cudaFuncSetAttribute(attn3_k, cudaFuncAttributeMaxDynamicSharedMemorySize, smem);
    attn3_k<<<dim3(18, NB * NHEAD), 256, smem>>>(q, k, vt, o);

    // output projections
    sgemm_tc<<<dim3(12, 32), 256>>>(o, Woi, boi, out,
                                    4096, 1536, 1536,
                                    SINP, SCTX, NTOK,
                                    BIG, 0, 0, 1536);
    sgemm_tc<<<dim3(12, 4), 256>>>(o, Woc, boc, out + (size_t)NB * SINP * DMODEL,
                                   512, 1536, 1536,
                                   SCTX, 0, NTOK,
                                   BIG, 0, 0, 1536);
}

// round 9
// speedup vs baseline: 2.8175x; 1.0791x over previous
#include <cuda_runtime.h>
#include <cuda_bf16.h>
#include <math.h>

#define NHEAD 12
#define HD    128
#define DMODEL 1536
#define SCTX  256
#define SINP  2048
#define NTOK  2304
#define NB    2

// ------------------------- scratch (device globals; no allocs allowed) ----
__device__ float g_qkv[(size_t)NB * NTOK * 3 * DMODEL];
__device__ float g_q[(size_t)NB * NHEAD * NTOK * HD];     // [b*h][tok][128]
__device__ float g_k[(size_t)NB * NHEAD * NTOK * HD];
__device__ float g_v[(size_t)NB * NHEAD * NTOK * HD];
__device__ float g_vt[(size_t)NB * NHEAD * HD * NTOK];    // [b*h][d][tok] (tf32-rounded)
__device__ float g_o[(size_t)NB * NTOK * DMODEL];

// row map: r(m) = (m/S)*Stride + Off + m%S   (S=1<<30 -> identity)
__device__ __forceinline__ int maprow(int m, int S, int off, int st) {
    return (m / S) * st + off + (m % S);
}

__device__ __forceinline__ float tf32_rn(float x) {
    unsigned r;
    asm("cvt.rna.tf32.f32 %0, %1;" : "=r"(r) : "f"(x));
    return __uint_as_float(r);
}

__device__ __forceinline__ void mma_tf32(float* d, const unsigned* a, const unsigned* b) {
    asm volatile(
        "mma.sync.aligned.m16n8k8.row.col.f32.tf32.tf32.f32 "
        "{%0,%1,%2,%3},{%4,%5,%6,%7},{%8,%9},{%0,%1,%2,%3};"
        : "+f"(d[0]), "+f"(d[1]), "+f"(d[2]), "+f"(d[3])
        : "r"(a[0]), "r"(a[1]), "r"(a[2]), "r"(a[3]), "r"(b[0]), "r"(b[1]));
}

__device__ __forceinline__ void mma_bf16(float* d, const unsigned* a, const unsigned* b) {
    asm volatile(
        "mma.sync.aligned.m16n8k16.row.col.f32.bf16.bf16.f32 "
        "{%0,%1,%2,%3},{%4,%5,%6,%7},{%8,%9},{%0,%1,%2,%3};"
        : "+f"(d[0]), "+f"(d[1]), "+f"(d[2]), "+f"(d[3])
        : "r"(a[0]), "r"(a[1]), "r"(a[2]), "r"(a[3]), "r"(b[0]), "r"(b[1]));
}

// pack two floats into bf16x2: lo_e -> low 16 bits (even k), hi_e -> high
__device__ __forceinline__ unsigned pack_bf16x2(float lo_e, float hi_e) {
    unsigned u;
    asm("cvt.rn.bf16x2.f32 %0, %1, %2;" : "=r"(u) : "f"(hi_e), "f"(lo_e));
    return u;
}

// split (x,y) [consecutive k] into packed hi and lo bf16x2 words
__device__ __forceinline__ void split_pack(float x, float y, unsigned& hi, unsigned& lo) {
    float hx = __bfloat162float(__float2bfloat16_rn(x));
    float hy = __bfloat162float(__float2bfloat16_rn(y));
    hi = pack_bf16x2(hx, hy);
    lo = pack_bf16x2(x - hx, y - hy);   // exact residual, then rn to bf16
}

// ------------------------- bf16 3-term split GEMM (fp32-accurate) ---------
// C[crow(m)][bn+*] = A[arow(m)][:] @ B[:, bn+*] + bias
// BM=BN=128, BK=16, 256 threads, warp grid 4(m)x2(n), warp tile 32x64.
// A,B stored as packed bf16x2 (k-pairs) hi/lo planes; result = ah*bh+ah*bl+al*bh.
__global__ __launch_bounds__(256, 2) void sgemm_tc(
    const float* __restrict__ A, const float* __restrict__ Bm,
    const float* __restrict__ bias, float* __restrict__ C,
    int M, int N, int K,
    int aS, int aOff, int aStride,
    int cS, int cOff, int cStride, int ldc)
{
    __shared__ unsigned Ah[2][8][128], Al[2][8][128];   // [buf][kpair][m ^ ((kp&3)<<3)]
    __shared__ unsigned Bh[2][8][128], Bl[2][8][128];   // [buf][kpair][n ^ ((kp&3)<<3)]

    int tid = threadIdx.x;
    int bm = blockIdx.y * 128, bn = blockIdx.x * 128;

    // A fill mapping: thread owns rows (arow, arow+64), k-cols [k4, k4+4)
    int arow = tid >> 2;
    int k4 = (tid & 3) * 4;
    int kp0 = (tid & 3) * 2;
    const float* aptr0 = A + (size_t)maprow(bm + arow,      aS, aOff, aStride) * K + k4;
    const float* aptr1 = A + (size_t)maprow(bm + arow + 64, aS, aOff, aStride) * K + k4;
    int ca0 = arow ^ ((kp0 & 3) << 3);
    int ca1 = arow ^ (((kp0 + 1) & 3) << 3);
    int cb0 = (arow + 64) ^ ((kp0 & 3) << 3);
    int cb1 = (arow + 64) ^ (((kp0 + 1) & 3) << 3);

    // B fill mapping: warp bw owns k-pair row bw (gmem rows 2bw, 2bw+1)
    int bw = tid >> 5;
    int bcol = (tid & 31) * 4;
    const float* bptr0 = Bm + (size_t)(2 * bw) * N + bn + bcol;
    const float* bptr1 = Bm + (size_t)(2 * bw + 1) * N + bn + bcol;
    int cbb = bcol ^ ((bw & 3) << 3);

    // warp/lane decomposition
    int warp = tid >> 5;
    int wm = warp & 3, wn = warp >> 2;
    int lane = tid & 31;
    int lg = lane >> 2, lt = lane & 3;

    float acc[2][8][4];
#pragma unroll
    for (int mi = 0; mi < 2; mi++)
#pragma unroll
        for (int nf = 0; nf < 8; nf++)
#pragma unroll
            for (int r = 0; r < 4; r++) acc[mi][nf][r] = 0.f;

    int ntiles = K / 16;

    float4 ra0, ra1, rb0, rb1;

    // prologue: load tile 0, commit to buffer 0
    ra0 = *(const float4*)aptr0;
    ra1 = *(const float4*)aptr1;
    rb0 = *(const float4*)bptr0;
    rb1 = *(const float4*)bptr1;
    {
        unsigned h0, l0, h1, l1;
        split_pack(ra0.x, ra0.y, h0, l0); split_pack(ra0.z, ra0.w, h1, l1);
        Ah[0][kp0][ca0] = h0; Al[0][kp0][ca0] = l0;
        Ah[0][kp0 + 1][ca1] = h1; Al[0][kp0 + 1][ca1] = l1;
        split_pack(ra1.x, ra1.y, h0, l0); split_pack(ra1.z, ra1.w, h1, l1);
        Ah[0][kp0][cb0] = h0; Al[0][kp0][cb0] = l0;
        Ah[0][kp0 + 1][cb1] = h1; Al[0][kp0 + 1][cb1] = l1;
        unsigned bh4[4], bl4[4];
        split_pack(rb0.x, rb1.x, bh4[0], bl4[0]);
        split_pack(rb0.y, rb1.y, bh4[1], bl4[1]);
        split_pack(rb0.z, rb1.z, bh4[2], bl4[2]);
        split_pack(rb0.w, rb1.w, bh4[3], bl4[3]);
        *(uint4*)&Bh[0][bw][cbb] = make_uint4(bh4[0], bh4[1], bh4[2], bh4[3]);
        *(uint4*)&Bl[0][bw][cbb] = make_uint4(bl4[0], bl4[1], bl4[2], bl4[3]);
    }
    __syncthreads();

    for (int t = 0; t < ntiles; t++) {
        int cur = t & 1;
        // prefetch next tile into registers
        if (t + 1 < ntiles) {
            ra0 = *(const float4*)(aptr0 + (size_t)(t + 1) * 16);
            ra1 = *(const float4*)(aptr1 + (size_t)(t + 1) * 16);
            rb0 = *(const float4*)(bptr0 + (size_t)(t + 1) * 16 * N);
            rb1 = *(const float4*)(bptr1 + (size_t)(t + 1) * 16 * N);
        }

        // ---- compute on current buffer: one k16 step ----
        unsigned ahf[2][4], alf[2][4];
#pragma unroll
        for (int mi = 0; mi < 2; mi++) {
            int m0 = wm * 32 + mi * 16 + lg;
            int x0 = m0 ^ (lt << 3), x1 = (m0 + 8) ^ (lt << 3);
            ahf[mi][0] = Ah[cur][lt][x0];
            ahf[mi][1] = Ah[cur][lt][x1];
            ahf[mi][2] = Ah[cur][lt + 4][x0];
            ahf[mi][3] = Ah[cur][lt + 4][x1];
            alf[mi][0] = Al[cur][lt][x0];
            alf[mi][1] = Al[cur][lt][x1];
            alf[mi][2] = Al[cur][lt + 4][x0];
            alf[mi][3] = Al[cur][lt + 4][x1];
        }
#pragma unroll
        for (int nf = 0; nf < 8; nf++) {
            int n = wn * 64 + nf * 8 + lg;
            int nx = n ^ (lt << 3);
            unsigned bhp[2] = { Bh[cur][lt][nx], Bh[cur][lt + 4][nx] };
            unsigned blp[2] = { Bl[cur][lt][nx], Bl[cur][lt + 4][nx] };
#pragma unroll
            for (int mi = 0; mi < 2; mi++) {
                mma_bf16(acc[mi][nf], ahf[mi], bhp);
                mma_bf16(acc[mi][nf], alf[mi], bhp);
                mma_bf16(acc[mi][nf], ahf[mi], blp);
            }
        }

        // commit prefetched tile to alternate buffer
        if (t + 1 < ntiles) {
            int alt = cur ^ 1;
            unsigned h0, l0, h1, l1;
            split_pack(ra0.x, ra0.y, h0, l0); split_pack(ra0.z, ra0.w, h1, l1);
            Ah[alt][kp0][ca0] = h0; Al[alt][kp0][ca0] = l0;
            Ah[alt][kp0 + 1][ca1] = h1; Al[alt][kp0 + 1][ca1] = l1;
            split_pack(ra1.x, ra1.y, h0, l0); split_pack(ra1.z, ra1.w, h1, l1);
            Ah[alt][kp0][cb0] = h0; Al[alt][kp0][cb0] = l0;
            Ah[alt][kp0 + 1][cb1] = h1; Al[alt][kp0 + 1][cb1] = l1;
            unsigned bh4[4], bl4[4];
            split_pack(rb0.x, rb1.x, bh4[0], bl4[0]);
            split_pack(rb0.y, rb1.y, bh4[1], bl4[1]);
            split_pack(rb0.z, rb1.z, bh4[2], bl4[2]);
            split_pack(rb0.w, rb1.w, bh4[3], bl4[3]);
            *(uint4*)&Bh[alt][bw][cbb] = make_uint4(bh4[0], bh4[1], bh4[2], bh4[3]);
            *(uint4*)&Bl[alt][bw][cbb] = make_uint4(bl4[0], bl4[1], bl4[2], bl4[3]);
        }
        __syncthreads();
    }

    // ---- epilogue: bias + remapped store ----
#pragma unroll
    for (int mi = 0; mi < 2; mi++) {
        int r0 = bm + wm * 32 + mi * 16 + lg;
        int cr0 = maprow(r0,     cS, cOff, cStride);
        int cr1 = maprow(r0 + 8, cS, cOff, cStride);
#pragma unroll
        for (int nf = 0; nf < 8; nf++) {
            int cn = bn + wn * 64 + nf * 8 + 2 * lt;
            float b0 = bias[cn], b1 = bias[cn + 1];
            float2 v0 = make_float2(acc[mi][nf][0] + b0, acc[mi][nf][1] + b1);
            float2 v1 = make_float2(acc[mi][nf][2] + b0, acc[mi][nf][3] + b1);
            *(float2*)&C[(size_t)cr0 * ldc + cn] = v0;
            *(float2*)&C[(size_t)cr1 * ldc + cn] = v1;
        }
    }
}

// ------------------------- fused RMSNorm + RoPE + head transpose ----------
__global__ __launch_bounds__(512) void norm_rope_k(
    const float* __restrict__ qkv,
    const float* __restrict__ qs_in, const float* __restrict__ ks_in,
    const float* __restrict__ qs_ctx, const float* __restrict__ ks_ctx,
    float* __restrict__ Q, float* __restrict__ K, float* __restrict__ V)
{
    __shared__ float sq[DMODEL], sk[DMODEL];
    __shared__ float cs_tab[64], sn_tab[64];
    __shared__ float wq[16], wk[16], ssum[2];

    int bt = blockIdx.x;
    int b = bt / NTOK, t = bt - b * NTOK;
    const float* row = qkv + (size_t)bt * (3 * DMODEL);
    bool is_ctx = (t < SCTX);
    const float* qs = is_ctx ? qs_ctx : qs_in;
    const float* ks = is_ctx ? ks_ctx : ks_in;
    int tid = threadIdx.x;

    if (tid < 64) {
        float invf = (float)pow(10000.0, -(double)tid / 64.0);
        float ang = (float)t * invf;
        cs_tab[tid] = (float)cos((double)ang);
        sn_tab[tid] = (float)sin((double)ang);
    }

    float aq = 0.f, ak = 0.f;
    float qv[3], kv[3], vv[3];
#pragma unroll
    for (int j = 0; j < 3; j++) {
        int i = tid + j * 512;
        qv[j] = row[i];
        kv[j] = row[DMODEL + i];
        vv[j] = row[2 * DMODEL + i];
        aq += qv[j] * qv[j];
        ak += kv[j] * kv[j];
    }
#pragma unroll
    for (int off = 16; off; off >>= 1) {
        aq += __shfl_xor_sync(0xffffffffu, aq, off);
        ak += __shfl_xor_sync(0xffffffffu, ak, off);
    }
    int wid = tid >> 5, lane = tid & 31;
    if (!lane) { wq[wid] = aq; wk[wid] = ak; }
    __syncthreads();
    if (tid == 0) {
        float s1 = 0.f, s2 = 0.f;
#pragma unroll
        for (int w = 0; w < 16; w++) { s1 += wq[w]; s2 += wk[w]; }
        ssum[0] = s1; ssum[1] = s2;
    }
    __syncthreads();
    float rq = rsqrtf(ssum[0] * (1.0f / DMODEL) + 1e-6f);
    float rk = rsqrtf(ssum[1] * (1.0f / DMODEL) + 1e-6f);
#pragma unroll
    for (int j = 0; j < 3; j++) {
        int i = tid + j * 512;
        sq[i] = qv[j] * rq * qs[i];
        sk[i] = kv[j] * rk * ks[i];
    }
    __syncthreads();
#pragma unroll
    for (int j = 0; j < 3; j++) {
        int i = tid + j * 512;
        int h = i >> 7, d = i & 127;
        int jj = d & 63;
        float cv = cs_tab[jj], sv = sn_tab[jj];
        int base = h * HD;
        float qo, ko;
        if (d < 64) {
            qo = sq[base + d] * cv - sq[base + d + 64] * sv;
            ko = sk[base + d] * cv - sk[base + d + 64] * sv;
        } else {
            qo = sq[base + d] * cv + sq[base + d - 64] * sv;
            ko = sk[base + d] * cv + sk[base + d - 64] * sv;
        }
        size_t o = ((size_t)(b * NHEAD + h) * NTOK + t) * HD + d;
        Q[o] = qo; K[o] = ko; V[o] = vv[j];
    }
}

// ------------------------- V transpose: [bh][tok][d] -> [bh][d][tok] ------
__global__ __launch_bounds__(256) void transpose_v(
    const float* __restrict__ V, float* __restrict__ Vt)
{
    __shared__ float tile[32][33];
    int bh = blockIdx.z;
    int t0 = blockIdx.x * 32, d0 = blockIdx.y * 32;
    int tx = threadIdx.x, ty = threadIdx.y;   // 32 x 8
    const float* src = V + ((size_t)bh * NTOK + t0) * HD + d0;
#pragma unroll
    for (int i = 0; i < 4; i++)
        tile[ty + 8 * i][tx] = src[(ty + 8 * i) * HD + tx];
    __syncthreads();
    float* dst = Vt + ((size_t)bh * HD + d0) * NTOK + t0;
#pragma unroll
    for (int i = 0; i < 4; i++)
        dst[(ty + 8 * i) * NTOK + tx] = tf32_rn(tile[tx][ty + 8 * i]);
}

// ------------------------- tf32 tensor-core flash attention ---------------
// BQ=BK=128, 256 threads, warp grid 4(m)x2(n), warp tile 32x64.
#define ALD 132
__global__ __launch_bounds__(256, 1) void attn3_k(
    const float* __restrict__ Q, const float* __restrict__ K,
    const float* __restrict__ Vt, float* __restrict__ O)
{
    extern __shared__ float smx[];
    float* Qs = smx;
    float* Ks = smx + 128 * ALD;
    float* Ps = Ks;
    float* Vs = smx + 2 * 128 * ALD;
    float* red = smx + 3 * 128 * ALD;   // [2][128][2]

    int tid = threadIdx.x;
    int warp = tid >> 5, lane = tid & 31;
    int wm = warp & 3, wn = warp >> 2;
    int lg = lane >> 2, lt = lane & 3;

    int qt = blockIdx.x, bh = blockIdx.y;
    int b = bh / NHEAD, h = bh - b * NHEAD;
    const float* Qb = Q + ((size_t)bh * NTOK + qt * 128) * HD;
    const float* Kb = K + (size_t)bh * NTOK * HD;
    const float* Vtb = Vt + (size_t)bh * HD * NTOK;

    // fill Q (tf32-rounded)
#pragma unroll
    for (int i = 0; i < 16; i++) {
        int f = tid + i * 256;
        int r = f >> 5, c4 = (f & 31) * 4;
        float4 v = *(const float4*)&Qb[r * HD + c4];
        *(float4*)&Qs[r * ALD + c4] =
            make_float4(tf32_rn(v.x), tf32_rn(v.y), tf32_rn(v.z), tf32_rn(v.w));
    }

    float m[2][2], l[2][2];
    float oacc[2][8][4];
#pragma unroll
    for (int mi = 0; mi < 2; mi++) {
        m[mi][0] = -INFINITY; m[mi][1] = -INFINITY;
        l[mi][0] = 0.f; l[mi][1] = 0.f;
#pragma unroll
        for (int nf = 0; nf < 8; nf++)
#pragma unroll
            for (int r = 0; r < 4; r++) oacc[mi][nf][r] = 0.f;
    }

    const float sc = 0.08838834764831845f;  // 1/sqrt(128)

    for (int kt = 0; kt < 18; kt++) {
        __syncthreads();

        // fill K tile [tok][d] and V tile [d][tok]
#pragma unroll
        for (int i = 0; i < 16; i++) {
            int f = tid + i * 256;
            int r = f >> 5, c4 = (f & 31) * 4;
            float4 kv = *(const float4*)&Kb[((size_t)(kt * 128 + r)) * HD + c4];
            *(float4*)&Ks[r * ALD + c4] =
                make_float4(tf32_rn(kv.x), tf32_rn(kv.y), tf32_rn(kv.z), tf32_rn(kv.w));
            *(float4*)&Vs[r * ALD + c4] =
                *(const float4*)&Vtb[(size_t)r * NTOK + kt * 128 + c4];
        }
        __syncthreads();

        // ---- S = Q K^T ----
        float sacc[2][8][4];
#pragma unroll
        for (int mi = 0; mi < 2; mi++)
#pragma unroll
            for (int nf = 0; nf < 8; nf++)
#pragma unroll
                for (int r = 0; r < 4; r++) sacc[mi][nf][r] = 0.f;

#pragma unroll
        for (int ks = 0; ks < 16; ks++) {
            int k = ks * 8;
            unsigned aq[2][4];
#pragma unroll
            for (int mi = 0; mi < 2; mi++) {
                int R = wm * 32 + mi * 16 + lg;
                aq[mi][0] = __float_as_uint(Qs[R * ALD + k + lt]);
                aq[mi][1] = __float_as_uint(Qs[(R + 8) * ALD + k + lt]);
                aq[mi][2] = __float_as_uint(Qs[R * ALD + k + lt + 4]);
                aq[mi][3] = __float_as_uint(Qs[(R + 8) * ALD + k + lt + 4]);
            }
            unsigned bk[8][2];
#pragma unroll
            for (int nf = 0; nf < 8; nf++) {
                int n = wn * 64 + nf * 8 + lg;
                bk[nf][0] = __float_as_uint(Ks[n * ALD + k + lt]);
                bk[nf][1] = __float_as_uint(Ks[n * ALD + k + lt + 4]);
            }
#pragma unroll
            for (int mi = 0; mi < 2; mi++)
#pragma unroll
                for (int nf = 0; nf < 8; nf++)
                    mma_tf32(sacc[mi][nf], aq[mi], bk[nf]);
        }

        // ---- warp-local row max, write partials ----
#pragma unroll
        for (int mi = 0; mi < 2; mi++) {
            int row0 = wm * 32 + mi * 16 + lg;
            float mx0 = -INFINITY, mx1 = -INFINITY;
#pragma unroll
            for (int nf = 0; nf < 8; nf++) {
                sacc[mi][nf][0] *= sc; sacc[mi][nf][1] *= sc;
                sacc[mi][nf][2] *= sc; sacc[mi][nf][3] *= sc;
                mx0 = fmaxf(mx0, fmaxf(sacc[mi][nf][0], sacc[mi][nf][1]));
                mx1 = fmaxf(mx1, fmaxf(sacc[mi][nf][2], sacc[mi][nf][3]));
            }
            mx0 = fmaxf(mx0, __shfl_xor_sync(0xffffffffu, mx0, 1));
            mx0 = fmaxf(mx0, __shfl_xor_sync(0xffffffffu, mx0, 2));
            mx1 = fmaxf(mx1, __shfl_xor_sync(0xffffffffu, mx1, 1));
            mx1 = fmaxf(mx1, __shfl_xor_sync(0xffffffffu, mx1, 2));
            if (lt == 0) {
                red[row0 * 2 + wn] = mx0;
                red[(row0 + 8) * 2 + wn] = mx1;
            }
        }
        __syncthreads();

        // ---- softmax ----
        float alpha[2][2];
#pragma unroll
        for (int mi = 0; mi < 2; mi++) {
            int row0 = wm * 32 + mi * 16 + lg;
            float gm0 = fmaxf(red[row0 * 2], red[row0 * 2 + 1]);
            float gm1 = fmaxf(red[(row0 + 8) * 2], red[(row0 + 8) * 2 + 1]);
            float mn0 = fmaxf(m[mi][0], gm0), mn1 = fmaxf(m[mi][1], gm1);
            alpha[mi][0] = __expf(m[mi][0] - mn0);
            alpha[mi][1] = __expf(m[mi][1] - mn1);
            m[mi][0] = mn0; m[mi][1] = mn1;
            float rs0 = 0.f, rs1 = 0.f;
#pragma unroll
            for (int nf = 0; nf < 8; nf++) {
                float p0 = tf32_rn(__expf(sacc[mi][nf][0] - mn0));
                float p1 = tf32_rn(__expf(sacc[mi][nf][1] - mn0));
                float p2 = tf32_rn(__expf(sacc[mi][nf][2] - mn1));
                float p3 = tf32_rn(__expf(sacc[mi][nf][3] - mn1));
                rs0 += p0 + p1; rs1 += p2 + p3;
                int col = wn * 64 + nf * 8 + 2 * lt;
                *(float2*)&Ps[row0 * ALD + col] = make_float2(p0, p1);
                *(float2*)&Ps[(row0 + 8) * ALD + col] = make_float2(p2, p3);
                oacc[mi][nf][0] *= alpha[mi][0];
                oacc[mi][nf][1] *= alpha[mi][0];
                oacc[mi][nf][2] *= alpha[mi][1];
                oacc[mi][nf][3] *= alpha[mi][1];
            }
            rs0 += __shfl_xor_sync(0xffffffffu, rs0, 1);
            rs0 += __shfl_xor_sync(0xffffffffu, rs0, 2);
            rs1 += __shfl_xor_sync(0xffffffffu, rs1, 1);
            rs1 += __shfl_xor_sync(0xffffffffu, rs1, 2);
            if (lt == 0) {
                red[256 + row0 * 2 + wn] = rs0;
                red[256 + (row0 + 8) * 2 + wn] = rs1;
            }
        }
        __syncthreads();

#pragma unroll
        for (int mi = 0; mi < 2; mi++) {
            int row0 = wm * 32 + mi * 16 + lg;
            l[mi][0] = l[mi][0] * alpha[mi][0]
                     + red[256 + row0 * 2] + red[256 + row0 * 2 + 1];
            l[mi][1] = l[mi][1] * alpha[mi][1]
                     + red[256 + (row0 + 8) * 2] + red[256 + (row0 + 8) * 2 + 1];
        }

        // ---- O += P V ----
#pragma unroll
        for (int ks = 0; ks < 16; ks++) {
            int k = ks * 8;
            unsigned ap[2][4];
#pragma unroll
            for (int mi = 0; mi < 2; mi++) {
                int R = wm * 32 + mi * 16 + lg;
                ap[mi][0] = __float_as_uint(Ps[R * ALD + k + lt]);
                ap[mi][1] = __float_as_uint(Ps[(R + 8) * ALD + k + lt]);
                ap[mi][2] = __float_as_uint(Ps[R * ALD + k + lt + 4]);
                ap[mi][3] = __float_as_uint(Ps[(R + 8) * ALD + k + lt + 4]);
            }
            unsigned bv[8][2];
#pragma unroll
            for (int nf = 0; nf < 8; nf++) {
                int n = wn * 64 + nf * 8 + lg;   // n = d
                bv[nf][0] = __float_as_uint(Vs[n * ALD + k + lt]);
                bv[nf][1] = __float_as_uint(Vs[n * ALD + k + lt + 4]);
            }
#pragma unroll
            for (int mi = 0; mi < 2; mi++)
#pragma unroll
                for (int nf = 0; nf < 8; nf++)
                    mma_tf32(oacc[mi][nf], ap[mi], bv[nf]);
        }
    }

    // ---- epilogue ----
#pragma unroll
    for (int mi = 0; mi < 2; mi++) {
        int row0 = wm * 32 + mi * 16 + lg;
        float inv0 = 1.0f / l[mi][0], inv1 = 1.0f / l[mi][1];
        size_t base0 = ((size_t)(b * NTOK + qt * 128 + row0)) * DMODEL + h * HD;
        size_t base1 = ((size_t)(b * NTOK + qt * 128 + row0 + 8)) * DMODEL + h * HD;
#pragma unroll
        for (int nf = 0; nf < 8; nf++) {
            int col = wn * 64 + nf * 8 + 2 * lt;
            *(float2*)&O[base0 + col] =
                make_float2(oacc[mi][nf][0] * inv0, oacc[mi][nf][1] * inv0);
            *(float2*)&O[base1 + col] =
                make_float2(oacc[mi][nf][2] * inv1, oacc[mi][nf][3] * inv1);
        }
    }
}

// ------------------------- launch -----------------------------------------
extern "C" void kernel_launch(void* const* d_in, const int* in_sizes, int n_in,
                              void* d_out, int out_size)
{
    const float* input   = (const float*)d_in[0];
    const float* context = (const float*)d_in[1];
    const float* Wqi = (const float*)d_in[2];
    const float* bqi = (const float*)d_in[3];
    const float* Wqc = (const float*)d_in[4];
    const float* bqc = (const float*)d_in[5];
    const float* qsi = (const float*)d_in[6];
    const float* ksi = (const float*)d_in[7];
    const float* qsc = (const float*)d_in[8];
    const float* ksc = (const float*)d_in[9];
    const float* Woi = (const float*)d_in[10];
    const float* boi = (const float*)d_in[11];
    const float* Woc = (const float*)d_in[12];
    const float* boc = (const float*)d_in[13];
    float* out = (float*)d_out;

    float *qkv, *q, *k, *v, *vt, *o;
    cudaGetSymbolAddress((void**)&qkv, g_qkv);
    cudaGetSymbolAddress((void**)&q,   g_q);
    cudaGetSymbolAddress((void**)&k,   g_k);
    cudaGetSymbolAddress((void**)&v,   g_v);
    cudaGetSymbolAddress((void**)&vt,  g_vt);
    cudaGetSymbolAddress((void**)&o,   g_o);

    const int BIG = 1 << 30;

    // QKV projections
    sgemm_tc<<<dim3(36, 32), 256>>>(input, Wqi, bqi, qkv,
                                    4096, 4608, 1536,
                                    BIG, 0, 0,
                                    SINP, SCTX, NTOK, 4608);
    sgemm_tc<<<dim3(36, 4), 256>>>(context, Wqc, bqc, qkv,
                                   512, 4608, 1536,
                                   BIG, 0, 0,
                                   SCTX, 0, NTOK, 4608);

    // RMSNorm + RoPE + transpose
    norm_rope_k<<<NB * NTOK, 512>>>(qkv, qsi, ksi, qsc, ksc, q, k, v);

    // V transpose (tf32-rounded) for the tensor-core PV GEMM
    transpose_v<<<dim3(NTOK / 32, HD / 32, NB * NHEAD), dim3(32, 8)>>>(v, vt);

    // tensor-core attention
    int smem = (3 * 128 * ALD + 512) * 4;
    cudaFuncSetAttribute(attn3_k, cudaFuncAttributeMaxDynamicSharedMemorySize, smem);
    attn3_k<<<dim3(18, NB * NHEAD), 256, smem>>>(q, k, vt, o);

    // output projections
    sgemm_tc<<<dim3(12, 32), 256>>>(o, Woi, boi, out,
                                    4096, 1536, 1536,
                                    SINP, SCTX, NTOK,
                                    BIG, 0, 0, 1536);
    sgemm_tc<<<dim3(12, 4), 256>>>(o, Woc, boc, out + (size_t)NB * SINP * DMODEL,
                                   512, 1536, 1536,
                                   SCTX, 0, NTOK,
                                   BIG, 0, 0, 1536);
}